// round 1
// baseline (speedup 1.0000x reference)
#include <cuda_runtime.h>
#include <cstdint>

// ---------------- scratch (device globals; no allocations allowed) ----------------
#define MAXNB 200000
#define MAXNC 20000
#define MAXE_GAT 200000

__device__ float g_hs[(size_t)MAXNB * 128];   // hs1 -> hs2 -> xw (reused sequentially)
__device__ float g_es[(size_t)MAXNB * 4];
__device__ float g_ed[(size_t)MAXNC * 4];
__device__ float g_sb[(size_t)MAXNC * 4];     // softmax denominators
__device__ float g_wb[(size_t)MAXE_GAT * 4];  // per-edge exp weights
__device__ float g_deg[MAXNB];                // deg -> dinv (in place)
__device__ float g_v1[128 * 4];               // Ws·a_s
__device__ float g_v2[128 * 4];               // Wd·a_d

static __device__ __forceinline__ void red_add_v4(float* addr, float x, float y, float z, float w) {
    asm volatile("red.global.add.v4.f32 [%0], {%1,%2,%3,%4};"
                 :: "l"(addr), "f"(x), "f"(y), "f"(z), "f"(w) : "memory");
}

// ---------------- GEMM: C[M,128] = A[M,128] @ W[128,128] (fp32) ----------------
#define GEMM_SMEM ((128 * 68 + 128 * 128) * 4)

__global__ void gemm128(const float* __restrict__ A, const float* __restrict__ W,
                        float* __restrict__ C, int M) {
    extern __shared__ float smem[];
    float* As  = smem;             // [128][68], transposed (k, row)
    float* Wsh = smem + 128 * 68;  // [128][128]
    int tid = threadIdx.x;
    int brow = blockIdx.x * 64;

    for (int i = tid; i < 128 * 32; i += 256)
        ((float4*)Wsh)[i] = ((const float4*)W)[i];
    for (int i = tid; i < 64 * 32; i += 256) {
        int r = i >> 5, c4 = i & 31;
        int row = brow + r;
        float4 v = make_float4(0.f, 0.f, 0.f, 0.f);
        if (row < M) v = ((const float4*)(A + (size_t)row * 128))[c4];
        int k0 = c4 * 4;
        As[(k0 + 0) * 68 + r] = v.x;
        As[(k0 + 1) * 68 + r] = v.y;
        As[(k0 + 2) * 68 + r] = v.z;
        As[(k0 + 3) * 68 + r] = v.w;
    }
    __syncthreads();

    int tx = tid & 15, ty = tid >> 4;  // tx: 16 col-groups of 8, ty: 16 row-groups of 4
    float acc[4][8];
#pragma unroll
    for (int r = 0; r < 4; r++)
#pragma unroll
        for (int c = 0; c < 8; c++) acc[r][c] = 0.f;

#pragma unroll 8
    for (int k = 0; k < 128; k++) {
        float4 a4 = *(const float4*)(As + k * 68 + ty * 4);
        float4 w0 = *(const float4*)(Wsh + k * 128 + tx * 8);
        float4 w1 = *(const float4*)(Wsh + k * 128 + tx * 8 + 4);
        float a[4] = {a4.x, a4.y, a4.z, a4.w};
        float w[8] = {w0.x, w0.y, w0.z, w0.w, w1.x, w1.y, w1.z, w1.w};
#pragma unroll
        for (int r = 0; r < 4; r++)
#pragma unroll
            for (int c = 0; c < 8; c++)
                acc[r][c] += a[r] * w[c];
    }

#pragma unroll
    for (int r = 0; r < 4; r++) {
        int row = brow + ty * 4 + r;
        if (row < M) {
            float4* cp = (float4*)(C + (size_t)row * 128 + tx * 8);
            cp[0] = make_float4(acc[r][0], acc[r][1], acc[r][2], acc[r][3]);
            cp[1] = make_float4(acc[r][4], acc[r][5], acc[r][6], acc[r][7]);
        }
    }
}

// V[d][h] = sum_c W[d, h*32+c] * a[h*32+c]   (one block of 128 threads)
__global__ void precompute_v(const float* __restrict__ W, const float* __restrict__ a,
                             float* __restrict__ V) {
    int d = threadIdx.x;
    float s[4] = {0.f, 0.f, 0.f, 0.f};
#pragma unroll
    for (int h = 0; h < 4; h++)
        for (int c = 0; c < 32; c++)
            s[h] += W[d * 128 + h * 32 + c] * a[h * 32 + c];
    ((float4*)V)[d] = make_float4(s[0], s[1], s[2], s[3]);
}

// out[n,h] = x[n,:] @ V[:,h]   (warp per node)
__global__ void node_alpha(const float* __restrict__ X, const float* __restrict__ V,
                           float* __restrict__ out, int N) {
    int gt = blockIdx.x * blockDim.x + threadIdx.x;
    int n = gt >> 5, lane = gt & 31;
    if (n >= N) return;
    float4 x = ((const float4*)(X + (size_t)n * 128))[lane];
    const float4* Vv = (const float4*)V;
    float xv[4] = {x.x, x.y, x.z, x.w};
    float s0 = 0.f, s1 = 0.f, s2 = 0.f, s3 = 0.f;
#pragma unroll
    for (int j = 0; j < 4; j++) {
        float4 v = Vv[lane * 4 + j];
        s0 += xv[j] * v.x; s1 += xv[j] * v.y;
        s2 += xv[j] * v.z; s3 += xv[j] * v.w;
    }
#pragma unroll
    for (int off = 16; off; off >>= 1) {
        s0 += __shfl_down_sync(~0u, s0, off);
        s1 += __shfl_down_sync(~0u, s1, off);
        s2 += __shfl_down_sync(~0u, s2, off);
        s3 += __shfl_down_sync(~0u, s3, off);
    }
    if (lane == 0) ((float4*)out)[n] = make_float4(s0, s1, s2, s3);
}

__global__ void zerok(float* __restrict__ p, int n) {
    int i = blockIdx.x * blockDim.x + threadIdx.x;
    if (i < n) p[i] = 0.f;
}

// per-edge: w = exp(leaky_relu(es[src]+ed[dst])), accumulate denominators
__global__ void edge_w(const float* __restrict__ es, const float* __restrict__ ed,
                       const int* __restrict__ src, const int* __restrict__ dst,
                       float* __restrict__ w, float* __restrict__ ssum, int E) {
    int e = blockIdx.x * blockDim.x + threadIdx.x;
    if (e >= E) return;
    int s = src[e], d = dst[e];
    float4 a = ((const float4*)es)[s];
    float4 b = ((const float4*)ed)[d];
    float t0 = a.x + b.x, t1 = a.y + b.y, t2 = a.z + b.z, t3 = a.w + b.w;
    t0 = t0 > 0.f ? t0 : 0.2f * t0;
    t1 = t1 > 0.f ? t1 : 0.2f * t1;
    t2 = t2 > 0.f ? t2 : 0.2f * t2;
    t3 = t3 > 0.f ? t3 : 0.2f * t3;
    float w0 = __expf(t0), w1 = __expf(t1), w2 = __expf(t2), w3 = __expf(t3);
    ((float4*)w)[e] = make_float4(w0, w1, w2, w3);
    red_add_v4(ssum + (size_t)d * 4, w0, w1, w2, w3);
}

// warp per edge: out[dst] += 0.5 * alpha * hs[src]
__global__ void edge_aggr(const float* __restrict__ w, const float* __restrict__ ssum,
                          const int* __restrict__ src, const int* __restrict__ dst,
                          const float* __restrict__ hs, float* __restrict__ out, int E) {
    int gt = blockIdx.x * blockDim.x + threadIdx.x;
    int e = gt >> 5, lane = gt & 31;
    if (e >= E) return;
    int s = src[e], d = dst[e];
    int h = lane >> 3;  // cols lane*4..lane*4+3 all within head h
    float alpha = w[(size_t)e * 4 + h] / (ssum[(size_t)d * 4 + h] + 1e-16f);
    float k = 0.5f * alpha;
    float4 hv = ((const float4*)(hs + (size_t)s * 128))[lane];
    red_add_v4(out + (size_t)d * 128 + lane * 4, k * hv.x, k * hv.y, k * hv.z, k * hv.w);
}

// out[n,c] = x[n,c] + 0.5*b[c]
__global__ void init_half_bias(const float* __restrict__ x, const float* __restrict__ b,
                               float* __restrict__ out, int N) {
    int i = blockIdx.x * blockDim.x + threadIdx.x;  // float4 index
    if (i >= N * 32) return;
    float4 xv = ((const float4*)x)[i];
    float4 bv = ((const float4*)b)[i & 31];
    ((float4*)out)[i] = make_float4(xv.x + 0.5f * bv.x, xv.y + 0.5f * bv.y,
                                    xv.z + 0.5f * bv.z, xv.w + 0.5f * bv.w);
}

__global__ void deg_count(const int* __restrict__ dst, float* __restrict__ deg, int E) {
    int e = blockIdx.x * blockDim.x + threadIdx.x;
    if (e < E) atomicAdd(deg + dst[e], 1.0f);
}

__global__ void deg_to_dinv(float* __restrict__ deg, int N) {
    int i = blockIdx.x * blockDim.x + threadIdx.x;
    if (i < N) deg[i] = rsqrtf(deg[i] + 1.0f);
}

// out[n,c] = x[n,c] + 0.2*(xw[n,c]*dinv[n]^2 + bg[c])
__global__ void init_building(const float* __restrict__ x, const float* __restrict__ xw,
                              const float* __restrict__ dinv, const float* __restrict__ bg,
                              float* __restrict__ out, int N) {
    int i = blockIdx.x * blockDim.x + threadIdx.x;  // float4 index
    if (i >= N * 32) return;
    int n = i >> 5;
    float di = dinv[n];
    float dd = di * di;
    float4 xv = ((const float4*)x)[i];
    float4 wv = ((const float4*)xw)[i];
    float4 bv = ((const float4*)bg)[i & 31];
    ((float4*)out)[i] = make_float4(xv.x + 0.2f * (wv.x * dd + bv.x),
                                    xv.y + 0.2f * (wv.y * dd + bv.y),
                                    xv.z + 0.2f * (wv.z * dd + bv.z),
                                    xv.w + 0.2f * (wv.w * dd + bv.w));
}

// warp per edge: out[dst] += 0.2 * dinv[src]*dinv[dst] * xw[src]
__global__ void gcn_edge(const int* __restrict__ src, const int* __restrict__ dst,
                         const float* __restrict__ xw, const float* __restrict__ dinv,
                         float* __restrict__ out, int E) {
    int gt = blockIdx.x * blockDim.x + threadIdx.x;
    int e = gt >> 5, lane = gt & 31;
    if (e >= E) return;
    int s = src[e], d = dst[e];
    float coef = 0.2f * dinv[s] * dinv[d];
    float4 v = ((const float4*)(xw + (size_t)s * 128))[lane];
    red_add_v4(out + (size_t)d * 128 + lane * 4,
               coef * v.x, coef * v.y, coef * v.z, coef * v.w);
}

// ---------------- launcher ----------------
static inline unsigned cdivu(long a, long b) { return (unsigned)((a + b - 1) / b); }

extern "C" void kernel_launch(void* const* d_in, const int* in_sizes, int n_in,
                              void* d_out, int out_size) {
    const float* xb  = (const float*)d_in[0];
    const float* xc  = (const float*)d_in[1];
    const float* xt  = (const float*)d_in[2];
    const float* Ws1 = (const float*)d_in[3];
    const float* Wd1 = (const float*)d_in[4];
    const float* as1 = (const float*)d_in[5];
    const float* ad1 = (const float*)d_in[6];
    const float* b1  = (const float*)d_in[7];
    const float* Ws2 = (const float*)d_in[8];
    const float* Wd2 = (const float*)d_in[9];
    const float* as2 = (const float*)d_in[10];
    const float* ad2 = (const float*)d_in[11];
    const float* b2  = (const float*)d_in[12];
    const float* Wg  = (const float*)d_in[13];
    const float* bg  = (const float*)d_in[14];
    const int* b2c_src = (const int*)d_in[15];
    const int* b2c_dst = (const int*)d_in[16];
    const int* c2t_src = (const int*)d_in[17];
    const int* c2t_dst = (const int*)d_in[18];
    const int* adj_src = (const int*)d_in[19];
    const int* adj_dst = (const int*)d_in[20];

    int Nb = in_sizes[0] / 128, Nc = in_sizes[1] / 128, Nt = in_sizes[2] / 128;
    int Ebc = in_sizes[15], Ect = in_sizes[17], Eadj = in_sizes[19];

    float* out   = (float*)d_out;
    float* out_b = out;
    float* out_c = out + (size_t)Nb * 128;
    float* out_t = out_c + (size_t)Nc * 128;

    void* p;
    cudaGetSymbolAddress(&p, g_hs);  float* hs   = (float*)p;
    cudaGetSymbolAddress(&p, g_es);  float* es   = (float*)p;
    cudaGetSymbolAddress(&p, g_ed);  float* ed   = (float*)p;
    cudaGetSymbolAddress(&p, g_sb);  float* sbuf = (float*)p;
    cudaGetSymbolAddress(&p, g_wb);  float* wbuf = (float*)p;
    cudaGetSymbolAddress(&p, g_deg); float* deg  = (float*)p;
    cudaGetSymbolAddress(&p, g_v1);  float* v1   = (float*)p;
    cudaGetSymbolAddress(&p, g_v2);  float* v2   = (float*)p;

    cudaFuncSetAttribute(gemm128, cudaFuncAttributeMaxDynamicSharedMemorySize, GEMM_SMEM);

    // ---------- GAT1: building -> cable ----------
    precompute_v<<<1, 128>>>(Ws1, as1, v1);
    precompute_v<<<1, 128>>>(Wd1, ad1, v2);
    gemm128<<<cdivu(Nb, 64), 256, GEMM_SMEM>>>(xb, Ws1, hs, Nb);
    node_alpha<<<cdivu((long)Nb * 32, 256), 256>>>(xb, v1, es, Nb);
    node_alpha<<<cdivu((long)Nc * 32, 256), 256>>>(xc, v2, ed, Nc);
    zerok<<<cdivu((long)Nc * 4, 256), 256>>>(sbuf, Nc * 4);
    edge_w<<<cdivu(Ebc, 256), 256>>>(es, ed, b2c_src, b2c_dst, wbuf, sbuf, Ebc);
    init_half_bias<<<cdivu((long)Nc * 32, 256), 256>>>(xc, b1, out_c, Nc);
    edge_aggr<<<cdivu((long)Ebc * 32, 256), 256>>>(wbuf, sbuf, b2c_src, b2c_dst, hs, out_c, Ebc);

    // ---------- GAT2: (updated) cable -> transformer ----------
    precompute_v<<<1, 128>>>(Ws2, as2, v1);
    precompute_v<<<1, 128>>>(Wd2, ad2, v2);
    gemm128<<<cdivu(Nc, 64), 256, GEMM_SMEM>>>(out_c, Ws2, hs, Nc);
    node_alpha<<<cdivu((long)Nc * 32, 256), 256>>>(out_c, v1, es, Nc);
    node_alpha<<<cdivu((long)Nt * 32, 256), 256>>>(xt, v2, ed, Nt);
    zerok<<<cdivu((long)Nt * 4, 256), 256>>>(sbuf, Nt * 4);
    edge_w<<<cdivu(Ect, 256), 256>>>(es, ed, c2t_src, c2t_dst, wbuf, sbuf, Ect);
    init_half_bias<<<cdivu((long)Nt * 32, 256), 256>>>(xt, b2, out_t, Nt);
    edge_aggr<<<cdivu((long)Ect * 32, 256), 256>>>(wbuf, sbuf, c2t_src, c2t_dst, hs, out_t, Ect);

    // ---------- GCN: building adjacency ----------
    gemm128<<<cdivu(Nb, 64), 256, GEMM_SMEM>>>(xb, Wg, hs, Nb);
    zerok<<<cdivu(Nb, 256), 256>>>(deg, Nb);
    deg_count<<<cdivu(Eadj, 256), 256>>>(adj_dst, deg, Eadj);
    deg_to_dinv<<<cdivu(Nb, 256), 256>>>(deg, Nb);
    init_building<<<cdivu((long)Nb * 32, 256), 256>>>(xb, hs, deg, bg, out_b, Nb);
    gcn_edge<<<cdivu((long)Eadj * 32, 256), 256>>>(adj_src, adj_dst, hs, deg, out_b, Eadj);
}

// round 2
// speedup vs baseline: 1.3361x; 1.3361x over previous
#include <cuda_runtime.h>
#include <cstdint>

// ---------------- scratch (device globals; no allocations allowed) ----------------
#define MAXNB 200000
#define MAXNC 20000
#define MAXE_GAT 200000

__device__ float g_hs[(size_t)MAXNB * 128];   // hs1 -> hs2 -> xw (reused sequentially)
__device__ float g_es[(size_t)MAXNB * 4];
__device__ float g_ed[(size_t)MAXNC * 4];
__device__ float g_sb[(size_t)MAXNC * 4];     // softmax denominators
__device__ float g_wb[(size_t)MAXE_GAT * 4];  // per-edge exp weights
__device__ float g_deg[MAXNB];                // deg -> dinv (in place)
__device__ float g_v2[128 * 4];               // Wd·a_d

static __device__ __forceinline__ void red_add_v4(float* addr, float x, float y, float z, float w) {
    asm volatile("red.global.add.v4.f32 [%0], {%1,%2,%3,%4};"
                 :: "l"(addr), "f"(x), "f"(y), "f"(z), "f"(w) : "memory");
}

// ---------------- GEMM: C[M,128] = A[M,128] @ W[128,128] (fp32, packed f32x2) -------
// Optional epilogue: es_out[n,h] = sum_c C[n, h*32+c] * a_s[h,c]
#define APAD 132
#define GEMM_SMEM ((128 * APAD + 128 * 128) * 4)

__global__ void __launch_bounds__(256, 1)
gemm128_x2(const float* __restrict__ A, const float* __restrict__ W,
           float* __restrict__ C, int M,
           float* __restrict__ es_out, const float* __restrict__ a_s) {
    extern __shared__ float smem[];
    float* As  = smem;               // [k=128][row, padded APAD]
    float* Wsh = smem + 128 * APAD;  // [k=128][col=128]
    int tid = threadIdx.x;
    int brow = blockIdx.x * 128;

    // load W (coalesced float4, conflict-free stores)
    for (int i = tid; i < 4096; i += 256)
        ((float4*)Wsh)[i] = ((const float4*)W)[i];

    // load A transposed: thread t owns row (t&127), k-half (t>>7)*64.
    // Stores: lanes have consecutive rows, same k -> conflict-free.
    {
        int row = tid & 127;
        int k0 = (tid >> 7) * 64;
        int grow = brow + row;
        const float4* Ar = (const float4*)(A + (size_t)grow * 128 + k0);
        bool ok = (grow < M);
#pragma unroll
        for (int i = 0; i < 16; i++) {
            float4 v = make_float4(0.f, 0.f, 0.f, 0.f);
            if (ok) v = Ar[i];
            int k = k0 + i * 4;
            As[(k + 0) * APAD + row] = v.x;
            As[(k + 1) * APAD + row] = v.y;
            As[(k + 2) * APAD + row] = v.z;
            As[(k + 3) * APAD + row] = v.w;
        }
    }
    __syncthreads();

    int tx = tid & 15, ty = tid >> 4;  // tx: 16 col-groups of 8; ty: 16 row-groups of 8
    unsigned long long acc[8][4];
#pragma unroll
    for (int r = 0; r < 8; r++)
#pragma unroll
        for (int j = 0; j < 4; j++) acc[r][j] = 0ull;

#pragma unroll 8
    for (int k = 0; k < 128; k++) {
        float4 a0 = *(const float4*)(As + k * APAD + ty * 8);
        float4 a1 = *(const float4*)(As + k * APAD + ty * 8 + 4);
        ulonglong2 W0 = *(const ulonglong2*)(Wsh + k * 128 + tx * 8);
        ulonglong2 W1 = *(const ulonglong2*)(Wsh + k * 128 + tx * 8 + 4);
        unsigned long long wp[4] = {W0.x, W0.y, W1.x, W1.y};
        float av[8] = {a0.x, a0.y, a0.z, a0.w, a1.x, a1.y, a1.z, a1.w};
#pragma unroll
        for (int r = 0; r < 8; r++) {
            unsigned long long a2;
            unsigned ai = __float_as_uint(av[r]);
            asm("mov.b64 %0, {%1, %1};" : "=l"(a2) : "r"(ai));
#pragma unroll
            for (int j = 0; j < 4; j++)
                asm("fma.rn.f32x2 %0, %1, %2, %0;" : "+l"(acc[r][j]) : "l"(a2), "l"(wp[j]));
        }
    }

    // store C
#pragma unroll
    for (int r = 0; r < 8; r++) {
        int row = brow + ty * 8 + r;
        if (row < M) {
            ulonglong2* cp = (ulonglong2*)(C + (size_t)row * 128 + tx * 8);
            cp[0] = make_ulonglong2(acc[r][0], acc[r][1]);
            cp[1] = make_ulonglong2(acc[r][2], acc[r][3]);
        }
    }

    // es epilogue: each thread covers cols tx*8..tx*8+7, all within head h = tx>>2
    if (es_out) {
        int h = tx >> 2;
        float asv[8];
#pragma unroll
        for (int c = 0; c < 8; c++) asv[c] = a_s[h * 32 + (tx & 3) * 8 + c];
#pragma unroll
        for (int r = 0; r < 8; r++) {
            float p = 0.f;
#pragma unroll
            for (int j = 0; j < 4; j++) {
                unsigned lo, hi;
                asm("mov.b64 {%0, %1}, %2;" : "=r"(lo), "=r"(hi) : "l"(acc[r][j]));
                p += __uint_as_float(lo) * asv[2 * j] + __uint_as_float(hi) * asv[2 * j + 1];
            }
            p += __shfl_down_sync(0xFFFFFFFFu, p, 1);
            p += __shfl_down_sync(0xFFFFFFFFu, p, 2);
            if ((tx & 3) == 0) {
                int row = brow + ty * 8 + r;
                if (row < M) es_out[(size_t)row * 4 + h] = p;
            }
        }
    }
}

// V[d][h] = sum_c W[d, h*32+c] * a[h*32+c]   (one block of 128 threads)
__global__ void precompute_v(const float* __restrict__ W, const float* __restrict__ a,
                             float* __restrict__ V) {
    int d = threadIdx.x;
    float s[4] = {0.f, 0.f, 0.f, 0.f};
#pragma unroll
    for (int h = 0; h < 4; h++)
        for (int c = 0; c < 32; c++)
            s[h] += W[d * 128 + h * 32 + c] * a[h * 32 + c];
    ((float4*)V)[d] = make_float4(s[0], s[1], s[2], s[3]);
}

// out[n,h] = x[n,:] @ V[:,h]   (warp per node)
__global__ void node_alpha(const float* __restrict__ X, const float* __restrict__ V,
                           float* __restrict__ out, int N) {
    int gt = blockIdx.x * blockDim.x + threadIdx.x;
    int n = gt >> 5, lane = gt & 31;
    if (n >= N) return;
    float4 x = ((const float4*)(X + (size_t)n * 128))[lane];
    const float4* Vv = (const float4*)V;
    float xv[4] = {x.x, x.y, x.z, x.w};
    float s0 = 0.f, s1 = 0.f, s2 = 0.f, s3 = 0.f;
#pragma unroll
    for (int j = 0; j < 4; j++) {
        float4 v = Vv[lane * 4 + j];
        s0 += xv[j] * v.x; s1 += xv[j] * v.y;
        s2 += xv[j] * v.z; s3 += xv[j] * v.w;
    }
#pragma unroll
    for (int off = 16; off; off >>= 1) {
        s0 += __shfl_down_sync(~0u, s0, off);
        s1 += __shfl_down_sync(~0u, s1, off);
        s2 += __shfl_down_sync(~0u, s2, off);
        s3 += __shfl_down_sync(~0u, s3, off);
    }
    if (lane == 0) ((float4*)out)[n] = make_float4(s0, s1, s2, s3);
}

__global__ void zerok(float* __restrict__ p, int n) {
    int i = blockIdx.x * blockDim.x + threadIdx.x;
    if (i < n) p[i] = 0.f;
}

// per-edge: w = exp(leaky_relu(es[src]+ed[dst])), accumulate denominators
__global__ void edge_w(const float* __restrict__ es, const float* __restrict__ ed,
                       const int* __restrict__ src, const int* __restrict__ dst,
                       float* __restrict__ w, float* __restrict__ ssum, int E) {
    int e = blockIdx.x * blockDim.x + threadIdx.x;
    if (e >= E) return;
    int s = src[e], d = dst[e];
    float4 a = ((const float4*)es)[s];
    float4 b = ((const float4*)ed)[d];
    float t0 = a.x + b.x, t1 = a.y + b.y, t2 = a.z + b.z, t3 = a.w + b.w;
    t0 = t0 > 0.f ? t0 : 0.2f * t0;
    t1 = t1 > 0.f ? t1 : 0.2f * t1;
    t2 = t2 > 0.f ? t2 : 0.2f * t2;
    t3 = t3 > 0.f ? t3 : 0.2f * t3;
    float w0 = __expf(t0), w1 = __expf(t1), w2 = __expf(t2), w3 = __expf(t3);
    ((float4*)w)[e] = make_float4(w0, w1, w2, w3);
    red_add_v4(ssum + (size_t)d * 4, w0, w1, w2, w3);
}

// warp per edge: out[dst] += 0.5 * alpha * hs[src]
__global__ void edge_aggr(const float* __restrict__ w, const float* __restrict__ ssum,
                          const int* __restrict__ src, const int* __restrict__ dst,
                          const float* __restrict__ hs, float* __restrict__ out, int E) {
    int gt = blockIdx.x * blockDim.x + threadIdx.x;
    int e = gt >> 5, lane = gt & 31;
    if (e >= E) return;
    int s = src[e], d = dst[e];
    int h = lane >> 3;
    float alpha = w[(size_t)e * 4 + h] / (ssum[(size_t)d * 4 + h] + 1e-16f);
    float k = 0.5f * alpha;
    float4 hv = ((const float4*)(hs + (size_t)s * 128))[lane];
    red_add_v4(out + (size_t)d * 128 + lane * 4, k * hv.x, k * hv.y, k * hv.z, k * hv.w);
}

// out[n,c] = x[n,c] + 0.5*b[c]
__global__ void init_half_bias(const float* __restrict__ x, const float* __restrict__ b,
                               float* __restrict__ out, int N) {
    int i = blockIdx.x * blockDim.x + threadIdx.x;  // float4 index
    if (i >= N * 32) return;
    float4 xv = ((const float4*)x)[i];
    float4 bv = ((const float4*)b)[i & 31];
    ((float4*)out)[i] = make_float4(xv.x + 0.5f * bv.x, xv.y + 0.5f * bv.y,
                                    xv.z + 0.5f * bv.z, xv.w + 0.5f * bv.w);
}

__global__ void deg_count(const int* __restrict__ dst, float* __restrict__ deg, int E) {
    int e = blockIdx.x * blockDim.x + threadIdx.x;
    if (e < E) atomicAdd(deg + dst[e], 1.0f);
}

__global__ void deg_to_dinv(float* __restrict__ deg, int N) {
    int i = blockIdx.x * blockDim.x + threadIdx.x;
    if (i < N) deg[i] = rsqrtf(deg[i] + 1.0f);
}

// out[n,c] = x[n,c] + 0.2*(xw[n,c]*dinv[n]^2 + bg[c])
__global__ void init_building(const float* __restrict__ x, const float* __restrict__ xw,
                              const float* __restrict__ dinv, const float* __restrict__ bg,
                              float* __restrict__ out, int N) {
    int i = blockIdx.x * blockDim.x + threadIdx.x;  // float4 index
    if (i >= N * 32) return;
    int n = i >> 5;
    float di = dinv[n];
    float dd = di * di;
    float4 xv = ((const float4*)x)[i];
    float4 wv = ((const float4*)xw)[i];
    float4 bv = ((const float4*)bg)[i & 31];
    ((float4*)out)[i] = make_float4(xv.x + 0.2f * (wv.x * dd + bv.x),
                                    xv.y + 0.2f * (wv.y * dd + bv.y),
                                    xv.z + 0.2f * (wv.z * dd + bv.z),
                                    xv.w + 0.2f * (wv.w * dd + bv.w));
}

// warp per edge: out[dst] += 0.2 * dinv[src]*dinv[dst] * xw[src]
__global__ void gcn_edge(const int* __restrict__ src, const int* __restrict__ dst,
                         const float* __restrict__ xw, const float* __restrict__ dinv,
                         float* __restrict__ out, int E) {
    int gt = blockIdx.x * blockDim.x + threadIdx.x;
    int e = gt >> 5, lane = gt & 31;
    if (e >= E) return;
    int s = src[e], d = dst[e];
    float coef = 0.2f * dinv[s] * dinv[d];
    float4 v = ((const float4*)(xw + (size_t)s * 128))[lane];
    red_add_v4(out + (size_t)d * 128 + lane * 4,
               coef * v.x, coef * v.y, coef * v.z, coef * v.w);
}

// ---------------- launcher ----------------
static inline unsigned cdivu(long a, long b) { return (unsigned)((a + b - 1) / b); }

extern "C" void kernel_launch(void* const* d_in, const int* in_sizes, int n_in,
                              void* d_out, int out_size) {
    const float* xb  = (const float*)d_in[0];
    const float* xc  = (const float*)d_in[1];
    const float* xt  = (const float*)d_in[2];
    const float* Ws1 = (const float*)d_in[3];
    const float* Wd1 = (const float*)d_in[4];
    const float* as1 = (const float*)d_in[5];
    const float* ad1 = (const float*)d_in[6];
    const float* b1  = (const float*)d_in[7];
    const float* Ws2 = (const float*)d_in[8];
    const float* Wd2 = (const float*)d_in[9];
    const float* as2 = (const float*)d_in[10];
    const float* ad2 = (const float*)d_in[11];
    const float* b2  = (const float*)d_in[12];
    const float* Wg  = (const float*)d_in[13];
    const float* bg  = (const float*)d_in[14];
    const int* b2c_src = (const int*)d_in[15];
    const int* b2c_dst = (const int*)d_in[16];
    const int* c2t_src = (const int*)d_in[17];
    const int* c2t_dst = (const int*)d_in[18];
    const int* adj_src = (const int*)d_in[19];
    const int* adj_dst = (const int*)d_in[20];

    int Nb = in_sizes[0] / 128, Nc = in_sizes[1] / 128, Nt = in_sizes[2] / 128;
    int Ebc = in_sizes[15], Ect = in_sizes[17], Eadj = in_sizes[19];

    float* out   = (float*)d_out;
    float* out_b = out;
    float* out_c = out + (size_t)Nb * 128;
    float* out_t = out_c + (size_t)Nc * 128;

    void* p;
    cudaGetSymbolAddress(&p, g_hs);  float* hs   = (float*)p;
    cudaGetSymbolAddress(&p, g_es);  float* es   = (float*)p;
    cudaGetSymbolAddress(&p, g_ed);  float* ed   = (float*)p;
    cudaGetSymbolAddress(&p, g_sb);  float* sbuf = (float*)p;
    cudaGetSymbolAddress(&p, g_wb);  float* wbuf = (float*)p;
    cudaGetSymbolAddress(&p, g_deg); float* deg  = (float*)p;
    cudaGetSymbolAddress(&p, g_v2);  float* v2   = (float*)p;

    cudaFuncSetAttribute(gemm128_x2, cudaFuncAttributeMaxDynamicSharedMemorySize, GEMM_SMEM);

    // ---------- GAT1: building -> cable ----------
    precompute_v<<<1, 128>>>(Wd1, ad1, v2);
    gemm128_x2<<<cdivu(Nb, 128), 256, GEMM_SMEM>>>(xb, Ws1, hs, Nb, es, as1);
    node_alpha<<<cdivu((long)Nc * 32, 256), 256>>>(xc, v2, ed, Nc);
    zerok<<<cdivu((long)Nc * 4, 256), 256>>>(sbuf, Nc * 4);
    edge_w<<<cdivu(Ebc, 256), 256>>>(es, ed, b2c_src, b2c_dst, wbuf, sbuf, Ebc);
    init_half_bias<<<cdivu((long)Nc * 32, 256), 256>>>(xc, b1, out_c, Nc);
    edge_aggr<<<cdivu((long)Ebc * 32, 256), 256>>>(wbuf, sbuf, b2c_src, b2c_dst, hs, out_c, Ebc);

    // ---------- GAT2: (updated) cable -> transformer ----------
    precompute_v<<<1, 128>>>(Wd2, ad2, v2);
    gemm128_x2<<<cdivu(Nc, 128), 256, GEMM_SMEM>>>(out_c, Ws2, hs, Nc, es, as2);
    node_alpha<<<cdivu((long)Nt * 32, 256), 256>>>(xt, v2, ed, Nt);
    zerok<<<cdivu((long)Nt * 4, 256), 256>>>(sbuf, Nt * 4);
    edge_w<<<cdivu(Ect, 256), 256>>>(es, ed, c2t_src, c2t_dst, wbuf, sbuf, Ect);
    init_half_bias<<<cdivu((long)Nt * 32, 256), 256>>>(xt, b2, out_t, Nt);
    edge_aggr<<<cdivu((long)Ect * 32, 256), 256>>>(wbuf, sbuf, c2t_src, c2t_dst, hs, out_t, Ect);

    // ---------- GCN: building adjacency ----------
    gemm128_x2<<<cdivu(Nb, 128), 256, GEMM_SMEM>>>(xb, Wg, hs, Nb, (float*)nullptr, bg);
    zerok<<<cdivu(Nb, 256), 256>>>(deg, Nb);
    deg_count<<<cdivu(Eadj, 256), 256>>>(adj_dst, deg, Eadj);
    deg_to_dinv<<<cdivu(Nb, 256), 256>>>(deg, Nb);
    init_building<<<cdivu((long)Nb * 32, 256), 256>>>(xb, hs, deg, bg, out_b, Nb);
    gcn_edge<<<cdivu((long)Eadj * 32, 256), 256>>>(adj_src, adj_dst, hs, deg, out_b, Eadj);
}

// round 3
// speedup vs baseline: 1.4702x; 1.1003x over previous
#include <cuda_runtime.h>
#include <cuda_bf16.h>
#include <cstdint>

// ---------------- scratch (device globals; no allocations allowed) ----------------
#define MAXNB 200000
#define MAXNC 20000
#define MAXE_GAT 200000

__device__ __nv_bfloat16 g_hs[(size_t)MAXNB * 128];  // hs1 -> hs2 -> xw (bf16)
__device__ float g_es[(size_t)MAXNB * 4];
__device__ float g_ed[(size_t)MAXNC * 4];
__device__ float g_sb[(size_t)MAXNC * 4];     // softmax denominators
__device__ float g_wb[(size_t)MAXE_GAT * 4];  // per-edge exp weights
__device__ float g_deg[MAXNB];                // deg -> dinv (in place)
__device__ float g_v2[128 * 4];               // Wd·a_d

static __device__ __forceinline__ void red_add_v4(float* addr, float x, float y, float z, float w) {
    asm volatile("red.global.add.v4.f32 [%0], {%1,%2,%3,%4};"
                 :: "l"(addr), "f"(x), "f"(y), "f"(z), "f"(w) : "memory");
}

// cvt two fp32 (c0 -> low half, c1 -> high half) to packed bf16x2
static __device__ __forceinline__ unsigned bf2pack(float c0, float c1) {
    unsigned r;
    asm("cvt.rn.bf16x2.f32 %0, %1, %2;" : "=r"(r) : "f"(c1), "f"(c0));
    return r;
}

// ---------------- GEMM: C[M,128] = A[M,128] @ W[128,128] (fp32, packed f32x2) -------
// C stored as bf16. Optional epilogue: es_out[n,h] = sum_c C[n, h*32+c] * a_s[h,c]
#define APAD 132
#define GEMM_SMEM ((128 * APAD + 128 * 128) * 4)

__global__ void __launch_bounds__(256, 1)
gemm128_x2(const float* __restrict__ A, const float* __restrict__ W,
           __nv_bfloat16* __restrict__ C, int M,
           float* __restrict__ es_out, const float* __restrict__ a_s) {
    extern __shared__ float smem[];
    float* As  = smem;               // [k=128][row, padded APAD]
    float* Wsh = smem + 128 * APAD;  // [k=128][col=128]
    int tid = threadIdx.x;
    int brow = blockIdx.x * 128;

    for (int i = tid; i < 4096; i += 256)
        ((float4*)Wsh)[i] = ((const float4*)W)[i];

    {
        int row = tid & 127;
        int k0 = (tid >> 7) * 64;
        int grow = brow + row;
        const float4* Ar = (const float4*)(A + (size_t)grow * 128 + k0);
        bool ok = (grow < M);
#pragma unroll
        for (int i = 0; i < 16; i++) {
            float4 v = make_float4(0.f, 0.f, 0.f, 0.f);
            if (ok) v = Ar[i];
            int k = k0 + i * 4;
            As[(k + 0) * APAD + row] = v.x;
            As[(k + 1) * APAD + row] = v.y;
            As[(k + 2) * APAD + row] = v.z;
            As[(k + 3) * APAD + row] = v.w;
        }
    }
    __syncthreads();

    int tx = tid & 15, ty = tid >> 4;
    unsigned long long acc[8][4];
#pragma unroll
    for (int r = 0; r < 8; r++)
#pragma unroll
        for (int j = 0; j < 4; j++) acc[r][j] = 0ull;

#pragma unroll 8
    for (int k = 0; k < 128; k++) {
        float4 a0 = *(const float4*)(As + k * APAD + ty * 8);
        float4 a1 = *(const float4*)(As + k * APAD + ty * 8 + 4);
        ulonglong2 W0 = *(const ulonglong2*)(Wsh + k * 128 + tx * 8);
        ulonglong2 W1 = *(const ulonglong2*)(Wsh + k * 128 + tx * 8 + 4);
        unsigned long long wp[4] = {W0.x, W0.y, W1.x, W1.y};
        float av[8] = {a0.x, a0.y, a0.z, a0.w, a1.x, a1.y, a1.z, a1.w};
#pragma unroll
        for (int r = 0; r < 8; r++) {
            unsigned long long a2;
            unsigned ai = __float_as_uint(av[r]);
            asm("mov.b64 %0, {%1, %1};" : "=l"(a2) : "r"(ai));
#pragma unroll
            for (int j = 0; j < 4; j++)
                asm("fma.rn.f32x2 %0, %1, %2, %0;" : "+l"(acc[r][j]) : "l"(a2), "l"(wp[j]));
        }
    }

    // store C as bf16: 8 cols per thread = 4 bf16x2 = uint4 (16B aligned)
#pragma unroll
    for (int r = 0; r < 8; r++) {
        int row = brow + ty * 8 + r;
        if (row < M) {
            uint4 pk;
            unsigned lo, hi;
            asm("mov.b64 {%0, %1}, %2;" : "=r"(lo), "=r"(hi) : "l"(acc[r][0]));
            pk.x = bf2pack(__uint_as_float(lo), __uint_as_float(hi));
            asm("mov.b64 {%0, %1}, %2;" : "=r"(lo), "=r"(hi) : "l"(acc[r][1]));
            pk.y = bf2pack(__uint_as_float(lo), __uint_as_float(hi));
            asm("mov.b64 {%0, %1}, %2;" : "=r"(lo), "=r"(hi) : "l"(acc[r][2]));
            pk.z = bf2pack(__uint_as_float(lo), __uint_as_float(hi));
            asm("mov.b64 {%0, %1}, %2;" : "=r"(lo), "=r"(hi) : "l"(acc[r][3]));
            pk.w = bf2pack(__uint_as_float(lo), __uint_as_float(hi));
            *(uint4*)(C + (size_t)row * 128 + tx * 8) = pk;
        }
    }

    // es epilogue from fp32 accumulators
    if (es_out) {
        int h = tx >> 2;
        float asv[8];
#pragma unroll
        for (int c = 0; c < 8; c++) asv[c] = a_s[h * 32 + (tx & 3) * 8 + c];
#pragma unroll
        for (int r = 0; r < 8; r++) {
            float p = 0.f;
#pragma unroll
            for (int j = 0; j < 4; j++) {
                unsigned lo, hi;
                asm("mov.b64 {%0, %1}, %2;" : "=r"(lo), "=r"(hi) : "l"(acc[r][j]));
                p += __uint_as_float(lo) * asv[2 * j] + __uint_as_float(hi) * asv[2 * j + 1];
            }
            p += __shfl_down_sync(0xFFFFFFFFu, p, 1);
            p += __shfl_down_sync(0xFFFFFFFFu, p, 2);
            if ((tx & 3) == 0) {
                int row = brow + ty * 8 + r;
                if (row < M) es_out[(size_t)row * 4 + h] = p;
            }
        }
    }
}

// V[d][h] = sum_c W[d, h*32+c] * a[h*32+c]
__global__ void precompute_v(const float* __restrict__ W, const float* __restrict__ a,
                             float* __restrict__ V) {
    int d = threadIdx.x;
    float s[4] = {0.f, 0.f, 0.f, 0.f};
#pragma unroll
    for (int h = 0; h < 4; h++)
        for (int c = 0; c < 32; c++)
            s[h] += W[d * 128 + h * 32 + c] * a[h * 32 + c];
    ((float4*)V)[d] = make_float4(s[0], s[1], s[2], s[3]);
}

// out[n,h] = x[n,:] @ V[:,h]   (warp per node)
__global__ void node_alpha(const float* __restrict__ X, const float* __restrict__ V,
                           float* __restrict__ out, int N) {
    int gt = blockIdx.x * blockDim.x + threadIdx.x;
    int n = gt >> 5, lane = gt & 31;
    if (n >= N) return;
    float4 x = ((const float4*)(X + (size_t)n * 128))[lane];
    const float4* Vv = (const float4*)V;
    float xv[4] = {x.x, x.y, x.z, x.w};
    float s0 = 0.f, s1 = 0.f, s2 = 0.f, s3 = 0.f;
#pragma unroll
    for (int j = 0; j < 4; j++) {
        float4 v = Vv[lane * 4 + j];
        s0 += xv[j] * v.x; s1 += xv[j] * v.y;
        s2 += xv[j] * v.z; s3 += xv[j] * v.w;
    }
#pragma unroll
    for (int off = 16; off; off >>= 1) {
        s0 += __shfl_down_sync(~0u, s0, off);
        s1 += __shfl_down_sync(~0u, s1, off);
        s2 += __shfl_down_sync(~0u, s2, off);
        s3 += __shfl_down_sync(~0u, s3, off);
    }
    if (lane == 0) ((float4*)out)[n] = make_float4(s0, s1, s2, s3);
}

__global__ void zerok(float* __restrict__ p, int n) {
    int i = blockIdx.x * blockDim.x + threadIdx.x;
    if (i < n) p[i] = 0.f;
}

// per-edge: w = exp(leaky_relu(es[src]+ed[dst])), accumulate denominators
__global__ void edge_w(const float* __restrict__ es, const float* __restrict__ ed,
                       const int* __restrict__ src, const int* __restrict__ dst,
                       float* __restrict__ w, float* __restrict__ ssum, int E) {
    int e = blockIdx.x * blockDim.x + threadIdx.x;
    if (e >= E) return;
    int s = src[e], d = dst[e];
    float4 a = ((const float4*)es)[s];
    float4 b = ((const float4*)ed)[d];
    float t0 = a.x + b.x, t1 = a.y + b.y, t2 = a.z + b.z, t3 = a.w + b.w;
    t0 = t0 > 0.f ? t0 : 0.2f * t0;
    t1 = t1 > 0.f ? t1 : 0.2f * t1;
    t2 = t2 > 0.f ? t2 : 0.2f * t2;
    t3 = t3 > 0.f ? t3 : 0.2f * t3;
    float w0 = __expf(t0), w1 = __expf(t1), w2 = __expf(t2), w3 = __expf(t3);
    ((float4*)w)[e] = make_float4(w0, w1, w2, w3);
    red_add_v4(ssum + (size_t)d * 4, w0, w1, w2, w3);
}

// warp per edge: out[dst] += 0.5 * alpha * hs_bf16[src]
__global__ void edge_aggr(const float* __restrict__ w, const float* __restrict__ ssum,
                          const int* __restrict__ src, const int* __restrict__ dst,
                          const __nv_bfloat16* __restrict__ hs, float* __restrict__ out, int E) {
    int gt = blockIdx.x * blockDim.x + threadIdx.x;
    int e = gt >> 5, lane = gt & 31;
    if (e >= E) return;
    int s = src[e], d = dst[e];
    int h = lane >> 3;
    float alpha = w[(size_t)e * 4 + h] / (ssum[(size_t)d * 4 + h] + 1e-16f);
    float k = 0.5f * alpha;
    uint2 raw = *(const uint2*)(hs + (size_t)s * 128 + lane * 4);
    float2 f0 = __bfloat1622float2(*(const __nv_bfloat162*)&raw.x);
    float2 f1 = __bfloat1622float2(*(const __nv_bfloat162*)&raw.y);
    red_add_v4(out + (size_t)d * 128 + lane * 4, k * f0.x, k * f0.y, k * f1.x, k * f1.y);
}

// out[n,c] = x[n,c] + 0.5*b[c]
__global__ void init_half_bias(const float* __restrict__ x, const float* __restrict__ b,
                               float* __restrict__ out, int N) {
    int i = blockIdx.x * blockDim.x + threadIdx.x;
    if (i >= N * 32) return;
    float4 xv = ((const float4*)x)[i];
    float4 bv = ((const float4*)b)[i & 31];
    ((float4*)out)[i] = make_float4(xv.x + 0.5f * bv.x, xv.y + 0.5f * bv.y,
                                    xv.z + 0.5f * bv.z, xv.w + 0.5f * bv.w);
}

__global__ void deg_count(const int* __restrict__ dst, float* __restrict__ deg, int E) {
    int e = blockIdx.x * blockDim.x + threadIdx.x;
    if (e < E) atomicAdd(deg + dst[e], 1.0f);
}

__global__ void deg_to_dinv(float* __restrict__ deg, int N) {
    int i = blockIdx.x * blockDim.x + threadIdx.x;
    if (i < N) deg[i] = rsqrtf(deg[i] + 1.0f);
}

// out[n,c] = x[n,c] + 0.2*(xw[n,c]*dinv[n]^2 + bg[c])   (xw in bf16)
__global__ void init_building(const float* __restrict__ x, const __nv_bfloat16* __restrict__ xw,
                              const float* __restrict__ dinv, const float* __restrict__ bg,
                              float* __restrict__ out, int N) {
    int i = blockIdx.x * blockDim.x + threadIdx.x;
    if (i >= N * 32) return;
    int n = i >> 5;
    float di = dinv[n];
    float dd = di * di;
    float4 xv = ((const float4*)x)[i];
    uint2 raw = ((const uint2*)xw)[i];
    float2 w0 = __bfloat1622float2(*(const __nv_bfloat162*)&raw.x);
    float2 w1 = __bfloat1622float2(*(const __nv_bfloat162*)&raw.y);
    float4 bv = ((const float4*)bg)[i & 31];
    ((float4*)out)[i] = make_float4(xv.x + 0.2f * (w0.x * dd + bv.x),
                                    xv.y + 0.2f * (w0.y * dd + bv.y),
                                    xv.z + 0.2f * (w1.x * dd + bv.z),
                                    xv.w + 0.2f * (w1.y * dd + bv.w));
}

// warp per edge: out[dst] += 0.2 * dinv[src]*dinv[dst] * xw_bf16[src]
__global__ void gcn_edge(const int* __restrict__ src, const int* __restrict__ dst,
                         const __nv_bfloat16* __restrict__ xw, const float* __restrict__ dinv,
                         float* __restrict__ out, int E) {
    int gt = blockIdx.x * blockDim.x + threadIdx.x;
    int e = gt >> 5, lane = gt & 31;
    if (e >= E) return;
    int s = src[e], d = dst[e];
    float coef = 0.2f * dinv[s] * dinv[d];
    uint2 raw = *(const uint2*)(xw + (size_t)s * 128 + lane * 4);
    float2 f0 = __bfloat1622float2(*(const __nv_bfloat162*)&raw.x);
    float2 f1 = __bfloat1622float2(*(const __nv_bfloat162*)&raw.y);
    red_add_v4(out + (size_t)d * 128 + lane * 4,
               coef * f0.x, coef * f0.y, coef * f1.x, coef * f1.y);
}

// ---------------- launcher ----------------
static inline unsigned cdivu(long a, long b) { return (unsigned)((a + b - 1) / b); }

extern "C" void kernel_launch(void* const* d_in, const int* in_sizes, int n_in,
                              void* d_out, int out_size) {
    const float* xb  = (const float*)d_in[0];
    const float* xc  = (const float*)d_in[1];
    const float* xt  = (const float*)d_in[2];
    const float* Ws1 = (const float*)d_in[3];
    const float* ad1 = (const float*)d_in[6];
    const float* Wd1 = (const float*)d_in[4];
    const float* as1 = (const float*)d_in[5];
    const float* b1  = (const float*)d_in[7];
    const float* Ws2 = (const float*)d_in[8];
    const float* Wd2 = (const float*)d_in[9];
    const float* as2 = (const float*)d_in[10];
    const float* ad2 = (const float*)d_in[11];
    const float* b2  = (const float*)d_in[12];
    const float* Wg  = (const float*)d_in[13];
    const float* bg  = (const float*)d_in[14];
    const int* b2c_src = (const int*)d_in[15];
    const int* b2c_dst = (const int*)d_in[16];
    const int* c2t_src = (const int*)d_in[17];
    const int* c2t_dst = (const int*)d_in[18];
    const int* adj_src = (const int*)d_in[19];
    const int* adj_dst = (const int*)d_in[20];

    int Nb = in_sizes[0] / 128, Nc = in_sizes[1] / 128, Nt = in_sizes[2] / 128;
    int Ebc = in_sizes[15], Ect = in_sizes[17], Eadj = in_sizes[19];

    float* out   = (float*)d_out;
    float* out_b = out;
    float* out_c = out + (size_t)Nb * 128;
    float* out_t = out_c + (size_t)Nc * 128;

    void* p;
    cudaGetSymbolAddress(&p, g_hs);  __nv_bfloat16* hs = (__nv_bfloat16*)p;
    cudaGetSymbolAddress(&p, g_es);  float* es   = (float*)p;
    cudaGetSymbolAddress(&p, g_ed);  float* ed   = (float*)p;
    cudaGetSymbolAddress(&p, g_sb);  float* sbuf = (float*)p;
    cudaGetSymbolAddress(&p, g_wb);  float* wbuf = (float*)p;
    cudaGetSymbolAddress(&p, g_deg); float* deg  = (float*)p;
    cudaGetSymbolAddress(&p, g_v2);  float* v2   = (float*)p;

    cudaFuncSetAttribute(gemm128_x2, cudaFuncAttributeMaxDynamicSharedMemorySize, GEMM_SMEM);

    // ---------- GAT1: building -> cable ----------
    precompute_v<<<1, 128>>>(Wd1, ad1, v2);
    gemm128_x2<<<cdivu(Nb, 128), 256, GEMM_SMEM>>>(xb, Ws1, hs, Nb, es, as1);
    node_alpha<<<cdivu((long)Nc * 32, 256), 256>>>(xc, v2, ed, Nc);
    zerok<<<cdivu((long)Nc * 4, 256), 256>>>(sbuf, Nc * 4);
    edge_w<<<cdivu(Ebc, 256), 256>>>(es, ed, b2c_src, b2c_dst, wbuf, sbuf, Ebc);
    init_half_bias<<<cdivu((long)Nc * 32, 256), 256>>>(xc, b1, out_c, Nc);
    edge_aggr<<<cdivu((long)Ebc * 32, 256), 256>>>(wbuf, sbuf, b2c_src, b2c_dst, hs, out_c, Ebc);

    // ---------- GAT2: (updated) cable -> transformer ----------
    precompute_v<<<1, 128>>>(Wd2, ad2, v2);
    gemm128_x2<<<cdivu(Nc, 128), 256, GEMM_SMEM>>>(out_c, Ws2, hs, Nc, es, as2);
    node_alpha<<<cdivu((long)Nt * 32, 256), 256>>>(xt, v2, ed, Nt);
    zerok<<<cdivu((long)Nt * 4, 256), 256>>>(sbuf, Nt * 4);
    edge_w<<<cdivu(Ect, 256), 256>>>(es, ed, c2t_src, c2t_dst, wbuf, sbuf, Ect);
    init_half_bias<<<cdivu((long)Nt * 32, 256), 256>>>(xt, b2, out_t, Nt);
    edge_aggr<<<cdivu((long)Ect * 32, 256), 256>>>(wbuf, sbuf, c2t_src, c2t_dst, hs, out_t, Ect);

    // ---------- GCN: building adjacency ----------
    gemm128_x2<<<cdivu(Nb, 128), 256, GEMM_SMEM>>>(xb, Wg, hs, Nb, (float*)nullptr, bg);
    zerok<<<cdivu(Nb, 256), 256>>>(deg, Nb);
    deg_count<<<cdivu(Eadj, 256), 256>>>(adj_dst, deg, Eadj);
    deg_to_dinv<<<cdivu(Nb, 256), 256>>>(deg, Nb);
    init_building<<<cdivu((long)Nb * 32, 256), 256>>>(xb, hs, deg, bg, out_b, Nb);
    gcn_edge<<<cdivu((long)Eadj * 32, 256), 256>>>(adj_src, adj_dst, hs, deg, out_b, Eadj);
}

// round 4
// speedup vs baseline: 1.7470x; 1.1883x over previous
#include <cuda_runtime.h>
#include <cuda_bf16.h>
#include <cstdint>

// ---------------- scratch (device globals; no allocations allowed) ----------------
#define MAXNB 200000
#define MAXNC 20000
#define MAXE_GAT 200000
#define MAXE_ADJ 1600000
#define SCAN_B 512

__device__ __nv_bfloat16 g_hs[(size_t)MAXNB * 128];  // hs1 -> hs2 -> xw (bf16)
__device__ float g_es[(size_t)MAXNB * 4];
__device__ float g_ed[(size_t)MAXNC * 4];
__device__ float g_sb[(size_t)MAXNC * 4];     // softmax denominators
__device__ float g_wb[(size_t)MAXE_GAT * 4];  // per-edge exp weights
__device__ float g_dinv[MAXNB];
__device__ int   g_cnt[MAXNB];                // counts, then reused as fill cursor
__device__ int   g_off[MAXNB + 1];            // exclusive CSR offsets
__device__ int   g_bsum[1024];
__device__ int   g_csrc[MAXE_ADJ];
__device__ float g_v2[128 * 4];               // Wd·a_d

static __device__ __forceinline__ void red_add_v4(float* addr, float x, float y, float z, float w) {
    asm volatile("red.global.add.v4.f32 [%0], {%1,%2,%3,%4};"
                 :: "l"(addr), "f"(x), "f"(y), "f"(z), "f"(w) : "memory");
}

static __device__ __forceinline__ unsigned bf2pack(float c0, float c1) {
    unsigned r;
    asm("cvt.rn.bf16x2.f32 %0, %1, %2;" : "=r"(r) : "f"(c1), "f"(c0));
    return r;
}

// ---------------- GEMM: C[M,128] = A[M,128] @ W[128,128] (fp32, packed f32x2) -------
#define APAD 132
#define GEMM_SMEM ((128 * APAD + 128 * 128) * 4)

__global__ void __launch_bounds__(256, 1)
gemm128_x2(const float* __restrict__ A, const float* __restrict__ W,
           __nv_bfloat16* __restrict__ C, int M,
           float* __restrict__ es_out, const float* __restrict__ a_s) {
    extern __shared__ float smem[];
    float* As  = smem;               // [k=128][row, padded APAD]
    float* Wsh = smem + 128 * APAD;  // [k=128][col=128]
    int tid = threadIdx.x;
    int brow = blockIdx.x * 128;

    for (int i = tid; i < 4096; i += 256)
        ((float4*)Wsh)[i] = ((const float4*)W)[i];

    {
        int row = tid & 127;
        int k0 = (tid >> 7) * 64;
        int grow = brow + row;
        const float4* Ar = (const float4*)(A + (size_t)grow * 128 + k0);
        bool ok = (grow < M);
#pragma unroll
        for (int i = 0; i < 16; i++) {
            float4 v = make_float4(0.f, 0.f, 0.f, 0.f);
            if (ok) v = Ar[i];
            int k = k0 + i * 4;
            As[(k + 0) * APAD + row] = v.x;
            As[(k + 1) * APAD + row] = v.y;
            As[(k + 2) * APAD + row] = v.z;
            As[(k + 3) * APAD + row] = v.w;
        }
    }
    __syncthreads();

    int tx = tid & 15, ty = tid >> 4;
    unsigned long long acc[8][4];
#pragma unroll
    for (int r = 0; r < 8; r++)
#pragma unroll
        for (int j = 0; j < 4; j++) acc[r][j] = 0ull;

#pragma unroll 8
    for (int k = 0; k < 128; k++) {
        float4 a0 = *(const float4*)(As + k * APAD + ty * 8);
        float4 a1 = *(const float4*)(As + k * APAD + ty * 8 + 4);
        ulonglong2 W0 = *(const ulonglong2*)(Wsh + k * 128 + tx * 8);
        ulonglong2 W1 = *(const ulonglong2*)(Wsh + k * 128 + tx * 8 + 4);
        unsigned long long wp[4] = {W0.x, W0.y, W1.x, W1.y};
        float av[8] = {a0.x, a0.y, a0.z, a0.w, a1.x, a1.y, a1.z, a1.w};
#pragma unroll
        for (int r = 0; r < 8; r++) {
            unsigned long long a2;
            unsigned ai = __float_as_uint(av[r]);
            asm("mov.b64 %0, {%1, %1};" : "=l"(a2) : "r"(ai));
#pragma unroll
            for (int j = 0; j < 4; j++)
                asm("fma.rn.f32x2 %0, %1, %2, %0;" : "+l"(acc[r][j]) : "l"(a2), "l"(wp[j]));
        }
    }

#pragma unroll
    for (int r = 0; r < 8; r++) {
        int row = brow + ty * 8 + r;
        if (row < M) {
            uint4 pk;
            unsigned lo, hi;
            asm("mov.b64 {%0, %1}, %2;" : "=r"(lo), "=r"(hi) : "l"(acc[r][0]));
            pk.x = bf2pack(__uint_as_float(lo), __uint_as_float(hi));
            asm("mov.b64 {%0, %1}, %2;" : "=r"(lo), "=r"(hi) : "l"(acc[r][1]));
            pk.y = bf2pack(__uint_as_float(lo), __uint_as_float(hi));
            asm("mov.b64 {%0, %1}, %2;" : "=r"(lo), "=r"(hi) : "l"(acc[r][2]));
            pk.z = bf2pack(__uint_as_float(lo), __uint_as_float(hi));
            asm("mov.b64 {%0, %1}, %2;" : "=r"(lo), "=r"(hi) : "l"(acc[r][3]));
            pk.w = bf2pack(__uint_as_float(lo), __uint_as_float(hi));
            *(uint4*)(C + (size_t)row * 128 + tx * 8) = pk;
        }
    }

    if (es_out) {
        int h = tx >> 2;
        float asv[8];
#pragma unroll
        for (int c = 0; c < 8; c++) asv[c] = a_s[h * 32 + (tx & 3) * 8 + c];
#pragma unroll
        for (int r = 0; r < 8; r++) {
            float p = 0.f;
#pragma unroll
            for (int j = 0; j < 4; j++) {
                unsigned lo, hi;
                asm("mov.b64 {%0, %1}, %2;" : "=r"(lo), "=r"(hi) : "l"(acc[r][j]));
                p += __uint_as_float(lo) * asv[2 * j] + __uint_as_float(hi) * asv[2 * j + 1];
            }
            p += __shfl_down_sync(0xFFFFFFFFu, p, 1);
            p += __shfl_down_sync(0xFFFFFFFFu, p, 2);
            if ((tx & 3) == 0) {
                int row = brow + ty * 8 + r;
                if (row < M) es_out[(size_t)row * 4 + h] = p;
            }
        }
    }
}

// V[d][h] = sum_c W[d, h*32+c] * a[h*32+c]
__global__ void precompute_v(const float* __restrict__ W, const float* __restrict__ a,
                             float* __restrict__ V) {
    int d = threadIdx.x;
    float s[4] = {0.f, 0.f, 0.f, 0.f};
#pragma unroll
    for (int h = 0; h < 4; h++)
        for (int c = 0; c < 32; c++)
            s[h] += W[d * 128 + h * 32 + c] * a[h * 32 + c];
    ((float4*)V)[d] = make_float4(s[0], s[1], s[2], s[3]);
}

// out[n,h] = x[n,:] @ V[:,h]   (warp per node)
__global__ void node_alpha(const float* __restrict__ X, const float* __restrict__ V,
                           float* __restrict__ out, int N) {
    int gt = blockIdx.x * blockDim.x + threadIdx.x;
    int n = gt >> 5, lane = gt & 31;
    if (n >= N) return;
    float4 x = ((const float4*)(X + (size_t)n * 128))[lane];
    const float4* Vv = (const float4*)V;
    float xv[4] = {x.x, x.y, x.z, x.w};
    float s0 = 0.f, s1 = 0.f, s2 = 0.f, s3 = 0.f;
#pragma unroll
    for (int j = 0; j < 4; j++) {
        float4 v = Vv[lane * 4 + j];
        s0 += xv[j] * v.x; s1 += xv[j] * v.y;
        s2 += xv[j] * v.z; s3 += xv[j] * v.w;
    }
#pragma unroll
    for (int off = 16; off; off >>= 1) {
        s0 += __shfl_down_sync(~0u, s0, off);
        s1 += __shfl_down_sync(~0u, s1, off);
        s2 += __shfl_down_sync(~0u, s2, off);
        s3 += __shfl_down_sync(~0u, s3, off);
    }
    if (lane == 0) ((float4*)out)[n] = make_float4(s0, s1, s2, s3);
}

// per-edge: w = exp(leaky_relu(es[src]+ed[dst])), accumulate denominators
__global__ void edge_w(const float* __restrict__ es, const float* __restrict__ ed,
                       const int* __restrict__ src, const int* __restrict__ dst,
                       float* __restrict__ w, float* __restrict__ ssum, int E) {
    int e = blockIdx.x * blockDim.x + threadIdx.x;
    if (e >= E) return;
    int s = src[e], d = dst[e];
    float4 a = ((const float4*)es)[s];
    float4 b = ((const float4*)ed)[d];
    float t0 = a.x + b.x, t1 = a.y + b.y, t2 = a.z + b.z, t3 = a.w + b.w;
    t0 = t0 > 0.f ? t0 : 0.2f * t0;
    t1 = t1 > 0.f ? t1 : 0.2f * t1;
    t2 = t2 > 0.f ? t2 : 0.2f * t2;
    t3 = t3 > 0.f ? t3 : 0.2f * t3;
    float w0 = __expf(t0), w1 = __expf(t1), w2 = __expf(t2), w3 = __expf(t3);
    ((float4*)w)[e] = make_float4(w0, w1, w2, w3);
    red_add_v4(ssum + (size_t)d * 4, w0, w1, w2, w3);
}

// warp per edge: out[dst] += 0.5 * alpha * hs_bf16[src]
__global__ void edge_aggr(const float* __restrict__ w, const float* __restrict__ ssum,
                          const int* __restrict__ src, const int* __restrict__ dst,
                          const __nv_bfloat16* __restrict__ hs, float* __restrict__ out, int E) {
    int gt = blockIdx.x * blockDim.x + threadIdx.x;
    int e = gt >> 5, lane = gt & 31;
    if (e >= E) return;
    int s = src[e], d = dst[e];
    int h = lane >> 3;
    float alpha = w[(size_t)e * 4 + h] / (ssum[(size_t)d * 4 + h] + 1e-16f);
    float k = 0.5f * alpha;
    uint2 raw = *(const uint2*)(hs + (size_t)s * 128 + lane * 4);
    float2 f0 = __bfloat1622float2(*(const __nv_bfloat162*)&raw.x);
    float2 f1 = __bfloat1622float2(*(const __nv_bfloat162*)&raw.y);
    red_add_v4(out + (size_t)d * 128 + lane * 4, k * f0.x, k * f0.y, k * f1.x, k * f1.y);
}

// out[n,c] = x[n,c] + 0.5*b[c]
__global__ void init_half_bias(const float* __restrict__ x, const float* __restrict__ b,
                               float* __restrict__ out, int N) {
    int i = blockIdx.x * blockDim.x + threadIdx.x;
    if (i >= N * 32) return;
    float4 xv = ((const float4*)x)[i];
    float4 bv = ((const float4*)b)[i & 31];
    ((float4*)out)[i] = make_float4(xv.x + 0.5f * bv.x, xv.y + 0.5f * bv.y,
                                    xv.z + 0.5f * bv.z, xv.w + 0.5f * bv.w);
}

// ---------------- GCN CSR build ----------------
__global__ void count_dst(const int* __restrict__ dst, int* __restrict__ cnt, int E) {
    int e = blockIdx.x * blockDim.x + threadIdx.x;
    if (e < E) atomicAdd(cnt + dst[e], 1);
}

__global__ void scan1(const int* __restrict__ cnt, int* __restrict__ incl,
                      int* __restrict__ bsum, int N) {
    int i = blockIdx.x * SCAN_B + threadIdx.x;
    int lane = threadIdx.x & 31, wid = threadIdx.x >> 5;
    int v = (i < N) ? cnt[i] : 0;
    int x = v;
#pragma unroll
    for (int o = 1; o < 32; o <<= 1) {
        int t = __shfl_up_sync(~0u, x, o);
        if (lane >= o) x += t;
    }
    __shared__ int wtot[16];
    if (lane == 31) wtot[wid] = x;
    __syncthreads();
    if (wid == 0) {
        int t = (lane < 16) ? wtot[lane] : 0;
#pragma unroll
        for (int o = 1; o < 16; o <<= 1) {
            int u = __shfl_up_sync(~0u, t, o);
            if (lane >= o) t += u;
        }
        if (lane < 16) wtot[lane] = t;
    }
    __syncthreads();
    int base = (wid > 0) ? wtot[wid - 1] : 0;
    int inclv = x + base;
    if (i < N) incl[i] = inclv;
    if (threadIdx.x == SCAN_B - 1) bsum[blockIdx.x] = inclv;
}

__global__ void scan2(int* __restrict__ bsum, int NB) {
    int i = threadIdx.x;
    int lane = i & 31, wid = i >> 5;
    int v = (i < NB) ? bsum[i] : 0;
    int x = v;
#pragma unroll
    for (int o = 1; o < 32; o <<= 1) {
        int t = __shfl_up_sync(~0u, x, o);
        if (lane >= o) x += t;
    }
    __shared__ int wtot[32];
    if (lane == 31) wtot[wid] = x;
    __syncthreads();
    if (wid == 0) {
        int t = wtot[lane];
#pragma unroll
        for (int o = 1; o < 32; o <<= 1) {
            int u = __shfl_up_sync(~0u, t, o);
            if (lane >= o) t += u;
        }
        wtot[lane] = t;
    }
    __syncthreads();
    int base = (wid > 0) ? wtot[wid - 1] : 0;
    if (i < NB) bsum[i] = x + base - v;  // exclusive
}

// finalize: off = exclusive, cursor = exclusive, dinv = rsqrt(cnt+1)
__global__ void scan3(int* __restrict__ cnt_cursor, int* __restrict__ off,
                      const int* __restrict__ bsum, float* __restrict__ dinv,
                      int N, int E) {
    int i = blockIdx.x * SCAN_B + threadIdx.x;
    if (i >= N) return;
    int c = cnt_cursor[i];
    int excl = off[i] - c + bsum[blockIdx.x];
    off[i] = excl;
    cnt_cursor[i] = excl;
    dinv[i] = rsqrtf((float)c + 1.0f);
    if (i == N - 1) off[N] = E;
}

__global__ void fill_csr(const int* __restrict__ src, const int* __restrict__ dst,
                         int* __restrict__ cursor, int* __restrict__ csrc, int E) {
    int e = blockIdx.x * blockDim.x + threadIdx.x;
    if (e >= E) return;
    int d = dst[e];
    int p = atomicAdd(cursor + d, 1);
    csrc[p] = src[e];
}

// warp per dst node: gather + finalize
__global__ void gcn_csr(const int* __restrict__ off, const int* __restrict__ csrc,
                        const float* __restrict__ dinv, const __nv_bfloat16* __restrict__ xw,
                        const float* __restrict__ xb, const float* __restrict__ bg,
                        float* __restrict__ out, int N) {
    int gt = blockIdx.x * blockDim.x + threadIdx.x;
    int n = gt >> 5, lane = gt & 31;
    if (n >= N) return;
    int o0 = off[n], o1 = off[n + 1];
    float a0 = 0.f, a1 = 0.f, a2 = 0.f, a3 = 0.f;
    for (int base = o0; base < o1; base += 32) {
        int eidx = base + lane;
        bool v = eidx < o1;
        int s_l = v ? csrc[eidx] : 0;
        float ds_l = v ? dinv[s_l] : 0.f;
        int cntc = min(32, o1 - base);
        for (int j = 0; j < cntc; j++) {
            int s = __shfl_sync(~0u, s_l, j);
            float ds = __shfl_sync(~0u, ds_l, j);
            uint2 raw = *(const uint2*)(xw + (size_t)s * 128 + lane * 4);
            float2 f0 = __bfloat1622float2(*(const __nv_bfloat162*)&raw.x);
            float2 f1 = __bfloat1622float2(*(const __nv_bfloat162*)&raw.y);
            a0 += ds * f0.x; a1 += ds * f0.y; a2 += ds * f1.x; a3 += ds * f1.y;
        }
    }
    float dn = dinv[n];
    float dd = dn * dn;
    float4 xv = *(const float4*)(xb + (size_t)n * 128 + lane * 4);
    uint2 rw = *(const uint2*)(xw + (size_t)n * 128 + lane * 4);
    float2 s0 = __bfloat1622float2(*(const __nv_bfloat162*)&rw.x);
    float2 s1 = __bfloat1622float2(*(const __nv_bfloat162*)&rw.y);
    float4 bv = *(const float4*)(bg + lane * 4);
    float4 o;
    o.x = xv.x + 0.2f * (dn * a0 + dd * s0.x + bv.x);
    o.y = xv.y + 0.2f * (dn * a1 + dd * s0.y + bv.y);
    o.z = xv.z + 0.2f * (dn * a2 + dd * s1.x + bv.z);
    o.w = xv.w + 0.2f * (dn * a3 + dd * s1.y + bv.w);
    *(float4*)(out + (size_t)n * 128 + lane * 4) = o;
}

// ---------------- launcher ----------------
static inline unsigned cdivu(long a, long b) { return (unsigned)((a + b - 1) / b); }

extern "C" void kernel_launch(void* const* d_in, const int* in_sizes, int n_in,
                              void* d_out, int out_size) {
    const float* xb  = (const float*)d_in[0];
    const float* xc  = (const float*)d_in[1];
    const float* xt  = (const float*)d_in[2];
    const float* Ws1 = (const float*)d_in[3];
    const float* Wd1 = (const float*)d_in[4];
    const float* as1 = (const float*)d_in[5];
    const float* ad1 = (const float*)d_in[6];
    const float* b1  = (const float*)d_in[7];
    const float* Ws2 = (const float*)d_in[8];
    const float* Wd2 = (const float*)d_in[9];
    const float* as2 = (const float*)d_in[10];
    const float* ad2 = (const float*)d_in[11];
    const float* b2  = (const float*)d_in[12];
    const float* Wg  = (const float*)d_in[13];
    const float* bg  = (const float*)d_in[14];
    const int* b2c_src = (const int*)d_in[15];
    const int* b2c_dst = (const int*)d_in[16];
    const int* c2t_src = (const int*)d_in[17];
    const int* c2t_dst = (const int*)d_in[18];
    const int* adj_src = (const int*)d_in[19];
    const int* adj_dst = (const int*)d_in[20];

    int Nb = in_sizes[0] / 128, Nc = in_sizes[1] / 128, Nt = in_sizes[2] / 128;
    int Ebc = in_sizes[15], Ect = in_sizes[17], Eadj = in_sizes[19];

    float* out   = (float*)d_out;
    float* out_b = out;
    float* out_c = out + (size_t)Nb * 128;
    float* out_t = out_c + (size_t)Nc * 128;

    void* p;
    cudaGetSymbolAddress(&p, g_hs);   __nv_bfloat16* hs = (__nv_bfloat16*)p;
    cudaGetSymbolAddress(&p, g_es);   float* es   = (float*)p;
    cudaGetSymbolAddress(&p, g_ed);   float* ed   = (float*)p;
    cudaGetSymbolAddress(&p, g_sb);   float* sbuf = (float*)p;
    cudaGetSymbolAddress(&p, g_wb);   float* wbuf = (float*)p;
    cudaGetSymbolAddress(&p, g_dinv); float* dinv = (float*)p;
    cudaGetSymbolAddress(&p, g_cnt);  int*   cnt  = (int*)p;
    cudaGetSymbolAddress(&p, g_off);  int*   off  = (int*)p;
    cudaGetSymbolAddress(&p, g_bsum); int*   bsum = (int*)p;
    cudaGetSymbolAddress(&p, g_csrc); int*   csrc = (int*)p;
    cudaGetSymbolAddress(&p, g_v2);   float* v2   = (float*)p;

    cudaFuncSetAttribute(gemm128_x2, cudaFuncAttributeMaxDynamicSharedMemorySize, GEMM_SMEM);

    // ---------- GAT1: building -> cable ----------
    precompute_v<<<1, 128>>>(Wd1, ad1, v2);
    gemm128_x2<<<cdivu(Nb, 128), 256, GEMM_SMEM>>>(xb, Ws1, hs, Nb, es, as1);
    node_alpha<<<cdivu((long)Nc * 32, 256), 256>>>(xc, v2, ed, Nc);
    cudaMemsetAsync(sbuf, 0, (size_t)Nc * 4 * sizeof(float), 0);
    edge_w<<<cdivu(Ebc, 256), 256>>>(es, ed, b2c_src, b2c_dst, wbuf, sbuf, Ebc);
    init_half_bias<<<cdivu((long)Nc * 32, 256), 256>>>(xc, b1, out_c, Nc);
    edge_aggr<<<cdivu((long)Ebc * 32, 256), 256>>>(wbuf, sbuf, b2c_src, b2c_dst, hs, out_c, Ebc);

    // ---------- GAT2: (updated) cable -> transformer ----------
    precompute_v<<<1, 128>>>(Wd2, ad2, v2);
    gemm128_x2<<<cdivu(Nc, 128), 256, GEMM_SMEM>>>(out_c, Ws2, hs, Nc, es, as2);
    node_alpha<<<cdivu((long)Nt * 32, 256), 256>>>(xt, v2, ed, Nt);
    cudaMemsetAsync(sbuf, 0, (size_t)Nt * 4 * sizeof(float), 0);
    edge_w<<<cdivu(Ect, 256), 256>>>(es, ed, c2t_src, c2t_dst, wbuf, sbuf, Ect);
    init_half_bias<<<cdivu((long)Nt * 32, 256), 256>>>(xt, b2, out_t, Nt);
    edge_aggr<<<cdivu((long)Ect * 32, 256), 256>>>(wbuf, sbuf, c2t_src, c2t_dst, hs, out_t, Ect);

    // ---------- GCN: building adjacency (CSR gather) ----------
    int NBb = cdivu(Nb, SCAN_B);
    cudaMemsetAsync(cnt, 0, (size_t)Nb * sizeof(int), 0);
    count_dst<<<cdivu(Eadj, 256), 256>>>(adj_dst, cnt, Eadj);
    scan1<<<NBb, SCAN_B>>>(cnt, off, bsum, Nb);
    scan2<<<1, 1024>>>(bsum, NBb);
    scan3<<<NBb, SCAN_B>>>(cnt, off, bsum, dinv, Nb, Eadj);
    fill_csr<<<cdivu(Eadj, 256), 256>>>(adj_src, adj_dst, cnt, csrc, Eadj);
    gemm128_x2<<<cdivu(Nb, 128), 256, GEMM_SMEM>>>(xb, Wg, hs, Nb, (float*)nullptr, bg);
    gcn_csr<<<cdivu((long)Nb * 32, 256), 256>>>(off, csrc, dinv, hs, xb, bg, out_b, Nb);
}

// round 6
// speedup vs baseline: 2.3110x; 1.3228x over previous
#include <cuda_runtime.h>
#include <cuda_bf16.h>
#include <cstdint>

// ---------------- scratch (device globals; no allocations allowed) ----------------
#define MAXNB 200000
#define MAXNC 20000
#define MAXE_GAT 200000
#define MAXE_ADJ 1600000
#define SCAN_B 512

__device__ __nv_bfloat16 g_hs[(size_t)MAXNB * 128];  // hs1 -> hs2 -> xw (bf16)
__device__ float g_es[(size_t)MAXNB * 4];
__device__ float g_ed[(size_t)MAXNC * 4];
__device__ float g_sb[(size_t)MAXNC * 4];
__device__ float g_wb[(size_t)MAXE_GAT * 4];
__device__ float g_dinv[MAXNB];
__device__ int   g_cnt[MAXNB];
__device__ int   g_off[MAXNB + 1];
__device__ int   g_bsum[1024];
__device__ int   g_csrc[MAXE_ADJ];
__device__ float g_v2[128 * 4];
__device__ float g_wt[128 * 128];              // transposed + tf32-rounded weight

static __device__ __forceinline__ void red_add_v4(float* addr, float x, float y, float z, float w) {
    asm volatile("red.global.add.v4.f32 [%0], {%1,%2,%3,%4};"
                 :: "l"(addr), "f"(x), "f"(y), "f"(z), "f"(w) : "memory");
}

static __device__ __forceinline__ unsigned bf2pack(float c0, float c1) {
    unsigned r;
    asm("cvt.rn.bf16x2.f32 %0, %1, %2;" : "=r"(r) : "f"(c1), "f"(c0));
    return r;
}

static __device__ __forceinline__ uint32_t tf32r(float v) {
    uint32_t r;
    asm("cvt.rna.tf32.f32 %0, %1;" : "=r"(r) : "f"(v));
    return r;
}

// W transposed ([n][k]) + tf32-rounded
__global__ void transpose_w_tf32(const float* __restrict__ W, float* __restrict__ Wt) {
    __shared__ float t[32][33];
    int bx = blockIdx.x * 32, by = blockIdx.y * 32;
#pragma unroll
    for (int j = 0; j < 32; j += 8) {
        float v = W[(size_t)(by + threadIdx.y + j) * 128 + bx + threadIdx.x];
        t[threadIdx.y + j][threadIdx.x] = __uint_as_float(tf32r(v));
    }
    __syncthreads();
#pragma unroll
    for (int j = 0; j < 32; j += 8)
        Wt[(size_t)(bx + threadIdx.y + j) * 128 + by + threadIdx.x] = t[threadIdx.x][threadIdx.y + j];
}

// ---------------- tf32 mma.sync GEMM: C[M,128] = A[M,128] @ W[128,128] ----------------
// Wt = [n][k] tf32-rounded. C stored bf16. Optional es epilogue.
#define AP 132
#define MMA_SMEM ((128 * AP * 2) * 4)

__global__ void __launch_bounds__(256, 1)
gemm_mma(const float* __restrict__ A, const float* __restrict__ Wt,
         __nv_bfloat16* __restrict__ C, int M,
         float* __restrict__ es_out, const float* __restrict__ a_s) {
    extern __shared__ float smem[];
    float* As = smem;             // [row][AP]
    float* Ws = smem + 128 * AP;  // [n][AP]
    int tid = threadIdx.x;
    int brow = blockIdx.x * 128;

    // stage A (tf32-rounded) and Wt into padded smem
    {
        int row = tid & 127;
        int k0 = (tid >> 7) * 64;
        int grow = brow + row;
        bool ok = grow < M;
        const float4* Ar = (const float4*)(A + (size_t)grow * 128 + k0);
        const float4* Wr = (const float4*)(Wt + (size_t)row * 128 + k0);
#pragma unroll
        for (int i = 0; i < 16; i++) {
            float4 v = make_float4(0.f, 0.f, 0.f, 0.f);
            if (ok) v = Ar[i];
            uint4 tv;
            tv.x = tf32r(v.x); tv.y = tf32r(v.y); tv.z = tf32r(v.z); tv.w = tf32r(v.w);
            *(uint4*)(As + row * AP + k0 + i * 4) = tv;
            *(float4*)(Ws + row * AP + k0 + i * 4) = Wr[i];
        }
    }
    __syncthreads();

    int wid = tid >> 5, lane = tid & 31;
    int g = lane >> 2, t = lane & 3;
    int wbase = wid * 16;

    float acc[16][4];
#pragma unroll
    for (int nt = 0; nt < 16; nt++)
#pragma unroll
        for (int j = 0; j < 4; j++) acc[nt][j] = 0.f;

    const uint32_t* Asu = (const uint32_t*)As;
    const uint32_t* Wsu = (const uint32_t*)Ws;
    int ar0 = (wbase + g) * AP, ar1 = (wbase + g + 8) * AP;

#pragma unroll 2
    for (int ks = 0; ks < 16; ks++) {
        int k0 = ks * 8;
        uint32_t a0 = Asu[ar0 + k0 + t];
        uint32_t a1 = Asu[ar1 + k0 + t];
        uint32_t a2 = Asu[ar0 + k0 + t + 4];
        uint32_t a3 = Asu[ar1 + k0 + t + 4];
#pragma unroll
        for (int nt = 0; nt < 16; nt++) {
            uint32_t b0 = Wsu[(nt * 8 + g) * AP + k0 + t];
            uint32_t b1 = Wsu[(nt * 8 + g) * AP + k0 + t + 4];
            asm("mma.sync.aligned.m16n8k8.row.col.f32.tf32.tf32.f32 "
                "{%0,%1,%2,%3}, {%4,%5,%6,%7}, {%8,%9}, {%0,%1,%2,%3};"
                : "+f"(acc[nt][0]), "+f"(acc[nt][1]), "+f"(acc[nt][2]), "+f"(acc[nt][3])
                : "r"(a0), "r"(a1), "r"(a2), "r"(a3), "r"(b0), "r"(b1));
        }
    }

    // epilogue: store bf16 C + optional es dot
    int grow0 = brow + wbase + g;
    int grow1 = grow0 + 8;
    bool ok0 = grow0 < M, ok1 = grow1 < M;
    float s0[4] = {0.f, 0.f, 0.f, 0.f}, s1[4] = {0.f, 0.f, 0.f, 0.f};
#pragma unroll
    for (int nt = 0; nt < 16; nt++) {
        float c0 = acc[nt][0], c1 = acc[nt][1], c2 = acc[nt][2], c3 = acc[nt][3];
        int col = nt * 8 + 2 * t;
        if (ok0) *(unsigned*)(C + (size_t)grow0 * 128 + col) = bf2pack(c0, c1);
        if (ok1) *(unsigned*)(C + (size_t)grow1 * 128 + col) = bf2pack(c2, c3);
        if (es_out) {
            int h = nt >> 2;
            int cb = h * 32 + (nt & 3) * 8 + 2 * t;
            float av0 = __ldg(a_s + cb), av1 = __ldg(a_s + cb + 1);
            s0[h] += c0 * av0 + c1 * av1;
            s1[h] += c2 * av0 + c3 * av1;
        }
    }
    if (es_out) {
#pragma unroll
        for (int j = 0; j < 4; j++) {
            s0[j] += __shfl_down_sync(~0u, s0[j], 1);
            s0[j] += __shfl_down_sync(~0u, s0[j], 2);
            s1[j] += __shfl_down_sync(~0u, s1[j], 1);
            s1[j] += __shfl_down_sync(~0u, s1[j], 2);
        }
        if (t == 0) {
            if (ok0) ((float4*)es_out)[grow0] = make_float4(s0[0], s0[1], s0[2], s0[3]);
            if (ok1) ((float4*)es_out)[grow1] = make_float4(s1[0], s1[1], s1[2], s1[3]);
        }
    }
}

// V[d][h] = sum_c W[d, h*32+c] * a[h*32+c]
__global__ void precompute_v(const float* __restrict__ W, const float* __restrict__ a,
                             float* __restrict__ V) {
    int d = threadIdx.x;
    float s[4] = {0.f, 0.f, 0.f, 0.f};
#pragma unroll
    for (int h = 0; h < 4; h++)
        for (int c = 0; c < 32; c++)
            s[h] += W[d * 128 + h * 32 + c] * a[h * 32 + c];
    ((float4*)V)[d] = make_float4(s[0], s[1], s[2], s[3]);
}

// out[n,h] = x[n,:] @ V[:,h]   (warp per node)
__global__ void node_alpha(const float* __restrict__ X, const float* __restrict__ V,
                           float* __restrict__ out, int N) {
    int gt = blockIdx.x * blockDim.x + threadIdx.x;
    int n = gt >> 5, lane = gt & 31;
    if (n >= N) return;
    float4 x = ((const float4*)(X + (size_t)n * 128))[lane];
    const float4* Vv = (const float4*)V;
    float xv[4] = {x.x, x.y, x.z, x.w};
    float s0 = 0.f, s1 = 0.f, s2 = 0.f, s3 = 0.f;
#pragma unroll
    for (int j = 0; j < 4; j++) {
        float4 v = Vv[lane * 4 + j];
        s0 += xv[j] * v.x; s1 += xv[j] * v.y;
        s2 += xv[j] * v.z; s3 += xv[j] * v.w;
    }
#pragma unroll
    for (int off = 16; off; off >>= 1) {
        s0 += __shfl_down_sync(~0u, s0, off);
        s1 += __shfl_down_sync(~0u, s1, off);
        s2 += __shfl_down_sync(~0u, s2, off);
        s3 += __shfl_down_sync(~0u, s3, off);
    }
    if (lane == 0) ((float4*)out)[n] = make_float4(s0, s1, s2, s3);
}

// per-edge: w = exp(leaky_relu(es[src]+ed[dst])), accumulate denominators
__global__ void edge_w(const float* __restrict__ es, const float* __restrict__ ed,
                       const int* __restrict__ src, const int* __restrict__ dst,
                       float* __restrict__ w, float* __restrict__ ssum, int E) {
    int e = blockIdx.x * blockDim.x + threadIdx.x;
    if (e >= E) return;
    int s = src[e], d = dst[e];
    float4 a = ((const float4*)es)[s];
    float4 b = ((const float4*)ed)[d];
    float t0 = a.x + b.x, t1 = a.y + b.y, t2 = a.z + b.z, t3 = a.w + b.w;
    t0 = t0 > 0.f ? t0 : 0.2f * t0;
    t1 = t1 > 0.f ? t1 : 0.2f * t1;
    t2 = t2 > 0.f ? t2 : 0.2f * t2;
    t3 = t3 > 0.f ? t3 : 0.2f * t3;
    float w0 = __expf(t0), w1 = __expf(t1), w2 = __expf(t2), w3 = __expf(t3);
    ((float4*)w)[e] = make_float4(w0, w1, w2, w3);
    red_add_v4(ssum + (size_t)d * 4, w0, w1, w2, w3);
}

// warp per edge: out[dst] += 0.5 * alpha * hs_bf16[src]
__global__ void edge_aggr(const float* __restrict__ w, const float* __restrict__ ssum,
                          const int* __restrict__ src, const int* __restrict__ dst,
                          const __nv_bfloat16* __restrict__ hs, float* __restrict__ out, int E) {
    int gt = blockIdx.x * blockDim.x + threadIdx.x;
    int e = gt >> 5, lane = gt & 31;
    if (e >= E) return;
    int s = src[e], d = dst[e];
    int h = lane >> 3;
    float alpha = w[(size_t)e * 4 + h] / (ssum[(size_t)d * 4 + h] + 1e-16f);
    float k = 0.5f * alpha;
    uint2 raw = *(const uint2*)(hs + (size_t)s * 128 + lane * 4);
    float2 f0 = __bfloat1622float2(*(const __nv_bfloat162*)&raw.x);
    float2 f1 = __bfloat1622float2(*(const __nv_bfloat162*)&raw.y);
    red_add_v4(out + (size_t)d * 128 + lane * 4, k * f0.x, k * f0.y, k * f1.x, k * f1.y);
}

// out[n,c] = x[n,c] + 0.5*b[c]
__global__ void init_half_bias(const float* __restrict__ x, const float* __restrict__ b,
                               float* __restrict__ out, int N) {
    int i = blockIdx.x * blockDim.x + threadIdx.x;
    if (i >= N * 32) return;
    float4 xv = ((const float4*)x)[i];
    float4 bv = ((const float4*)b)[i & 31];
    ((float4*)out)[i] = make_float4(xv.x + 0.5f * bv.x, xv.y + 0.5f * bv.y,
                                    xv.z + 0.5f * bv.z, xv.w + 0.5f * bv.w);
}

// ---------------- GCN CSR build ----------------
__global__ void count_dst(const int* __restrict__ dst, int* __restrict__ cnt, int E) {
    int e = blockIdx.x * blockDim.x + threadIdx.x;
    if (e < E) atomicAdd(cnt + dst[e], 1);
}

__global__ void scan1(const int* __restrict__ cnt, int* __restrict__ incl,
                      int* __restrict__ bsum, int N) {
    int i = blockIdx.x * SCAN_B + threadIdx.x;
    int lane = threadIdx.x & 31, wid = threadIdx.x >> 5;
    int v = (i < N) ? cnt[i] : 0;
    int x = v;
#pragma unroll
    for (int o = 1; o < 32; o <<= 1) {
        int t = __shfl_up_sync(~0u, x, o);
        if (lane >= o) x += t;
    }
    __shared__ int wtot[16];
    if (lane == 31) wtot[wid] = x;
    __syncthreads();
    if (wid == 0) {
        int t = (lane < 16) ? wtot[lane] : 0;
#pragma unroll
        for (int o = 1; o < 16; o <<= 1) {
            int u = __shfl_up_sync(~0u, t, o);
            if (lane >= o) t += u;
        }
        if (lane < 16) wtot[lane] = t;
    }
    __syncthreads();
    int base = (wid > 0) ? wtot[wid - 1] : 0;
    int inclv = x + base;
    if (i < N) incl[i] = inclv;
    if (threadIdx.x == SCAN_B - 1) bsum[blockIdx.x] = inclv;
}

__global__ void scan2(int* __restrict__ bsum, int NB) {
    int i = threadIdx.x;
    int lane = i & 31, wid = i >> 5;
    int v = (i < NB) ? bsum[i] : 0;
    int x = v;
#pragma unroll
    for (int o = 1; o < 32; o <<= 1) {
        int t = __shfl_up_sync(~0u, x, o);
        if (lane >= o) x += t;
    }
    __shared__ int wtot[32];
    if (lane == 31) wtot[wid] = x;
    __syncthreads();
    if (wid == 0) {
        int t = wtot[lane];
#pragma unroll
        for (int o = 1; o < 32; o <<= 1) {
            int u = __shfl_up_sync(~0u, t, o);
            if (lane >= o) t += u;
        }
        wtot[lane] = t;
    }
    __syncthreads();
    int base = (wid > 0) ? wtot[wid - 1] : 0;
    if (i < NB) bsum[i] = x + base - v;
}

__global__ void scan3(int* __restrict__ cnt_cursor, int* __restrict__ off,
                      const int* __restrict__ bsum, float* __restrict__ dinv,
                      int N, int E) {
    int i = blockIdx.x * SCAN_B + threadIdx.x;
    if (i >= N) return;
    int c = cnt_cursor[i];
    int excl = off[i] - c + bsum[blockIdx.x];
    off[i] = excl;
    cnt_cursor[i] = excl;
    dinv[i] = rsqrtf((float)c + 1.0f);
    if (i == N - 1) off[N] = E;
}

__global__ void fill_csr(const int* __restrict__ src, const int* __restrict__ dst,
                         int* __restrict__ cursor, int* __restrict__ csrc, int E) {
    int e = blockIdx.x * blockDim.x + threadIdx.x;
    if (e >= E) return;
    int d = dst[e];
    int p = atomicAdd(cursor + d, 1);
    csrc[p] = src[e];
}

// warp per dst node: gather + finalize
__global__ void gcn_csr(const int* __restrict__ off, const int* __restrict__ csrc,
                        const float* __restrict__ dinv, const __nv_bfloat16* __restrict__ xw,
                        const float* __restrict__ xb, const float* __restrict__ bg,
                        float* __restrict__ out, int N) {
    int gt = blockIdx.x * blockDim.x + threadIdx.x;
    int n = gt >> 5, lane = gt & 31;
    if (n >= N) return;
    int o0 = off[n], o1 = off[n + 1];
    float a0 = 0.f, a1 = 0.f, a2 = 0.f, a3 = 0.f;
    for (int base = o0; base < o1; base += 32) {
        int eidx = base + lane;
        bool v = eidx < o1;
        int s_l = v ? csrc[eidx] : 0;
        float ds_l = v ? dinv[s_l] : 0.f;
        int cntc = min(32, o1 - base);
        for (int j = 0; j < cntc; j++) {
            int s = __shfl_sync(~0u, s_l, j);
            float ds = __shfl_sync(~0u, ds_l, j);
            uint2 raw = *(const uint2*)(xw + (size_t)s * 128 + lane * 4);
            float2 f0 = __bfloat1622float2(*(const __nv_bfloat162*)&raw.x);
            float2 f1 = __bfloat1622float2(*(const __nv_bfloat162*)&raw.y);
            a0 += ds * f0.x; a1 += ds * f0.y; a2 += ds * f1.x; a3 += ds * f1.y;
        }
    }
    float dn = dinv[n];
    float dd = dn * dn;
    float4 xv = *(const float4*)(xb + (size_t)n * 128 + lane * 4);
    uint2 rw = *(const uint2*)(xw + (size_t)n * 128 + lane * 4);
    float2 s0 = __bfloat1622float2(*(const __nv_bfloat162*)&rw.x);
    float2 s1 = __bfloat1622float2(*(const __nv_bfloat162*)&rw.y);
    float4 bv = *(const float4*)(bg + lane * 4);
    float4 o;
    o.x = xv.x + 0.2f * (dn * a0 + dd * s0.x + bv.x);
    o.y = xv.y + 0.2f * (dn * a1 + dd * s0.y + bv.y);
    o.z = xv.z + 0.2f * (dn * a2 + dd * s1.x + bv.z);
    o.w = xv.w + 0.2f * (dn * a3 + dd * s1.y + bv.w);
    *(float4*)(out + (size_t)n * 128 + lane * 4) = o;
}

// ---------------- launcher ----------------
static inline unsigned cdivu(long a, long b) { return (unsigned)((a + b - 1) / b); }

extern "C" void kernel_launch(void* const* d_in, const int* in_sizes, int n_in,
                              void* d_out, int out_size) {
    const float* xb  = (const float*)d_in[0];
    const float* xc  = (const float*)d_in[1];
    const float* xt  = (const float*)d_in[2];
    const float* Ws1 = (const float*)d_in[3];
    const float* Wd1 = (const float*)d_in[4];
    const float* as1 = (const float*)d_in[5];
    const float* ad1 = (const float*)d_in[6];
    const float* b1  = (const float*)d_in[7];
    const float* Ws2 = (const float*)d_in[8];
    const float* Wd2 = (const float*)d_in[9];
    const float* as2 = (const float*)d_in[10];
    const float* ad2 = (const float*)d_in[11];
    const float* b2  = (const float*)d_in[12];
    const float* Wg  = (const float*)d_in[13];
    const float* bg  = (const float*)d_in[14];
    const int* b2c_src = (const int*)d_in[15];
    const int* b2c_dst = (const int*)d_in[16];
    const int* c2t_src = (const int*)d_in[17];
    const int* c2t_dst = (const int*)d_in[18];
    const int* adj_src = (const int*)d_in[19];
    const int* adj_dst = (const int*)d_in[20];

    int Nb = in_sizes[0] / 128, Nc = in_sizes[1] / 128, Nt = in_sizes[2] / 128;
    int Ebc = in_sizes[15], Ect = in_sizes[17], Eadj = in_sizes[19];

    float* out   = (float*)d_out;
    float* out_b = out;
    float* out_c = out + (size_t)Nb * 128;
    float* out_t = out_c + (size_t)Nc * 128;

    void* p;
    cudaGetSymbolAddress(&p, g_hs);   __nv_bfloat16* hs = (__nv_bfloat16*)p;
    cudaGetSymbolAddress(&p, g_es);   float* es   = (float*)p;
    cudaGetSymbolAddress(&p, g_ed);   float* ed   = (float*)p;
    cudaGetSymbolAddress(&p, g_sb);   float* sbuf = (float*)p;
    cudaGetSymbolAddress(&p, g_wb);   float* wbuf = (float*)p;
    cudaGetSymbolAddress(&p, g_dinv); float* dinv = (float*)p;
    cudaGetSymbolAddress(&p, g_cnt);  int*   cnt  = (int*)p;
    cudaGetSymbolAddress(&p, g_off);  int*   off  = (int*)p;
    cudaGetSymbolAddress(&p, g_bsum); int*   bsum = (int*)p;
    cudaGetSymbolAddress(&p, g_csrc); int*   csrc = (int*)p;
    cudaGetSymbolAddress(&p, g_v2);   float* v2   = (float*)p;
    cudaGetSymbolAddress(&p, g_wt);   float* wt   = (float*)p;

    cudaFuncSetAttribute(gemm_mma, cudaFuncAttributeMaxDynamicSharedMemorySize, MMA_SMEM);
    dim3 tg(4, 4), tb(32, 8);

    // ---------- GAT1: building -> cable ----------
    precompute_v<<<1, 128>>>(Wd1, ad1, v2);
    transpose_w_tf32<<<tg, tb>>>(Ws1, wt);
    gemm_mma<<<cdivu(Nb, 128), 256, MMA_SMEM>>>(xb, wt, hs, Nb, es, as1);
    node_alpha<<<cdivu((long)Nc * 32, 256), 256>>>(xc, v2, ed, Nc);
    cudaMemsetAsync(sbuf, 0, (size_t)Nc * 4 * sizeof(float), 0);
    edge_w<<<cdivu(Ebc, 256), 256>>>(es, ed, b2c_src, b2c_dst, wbuf, sbuf, Ebc);
    init_half_bias<<<cdivu((long)Nc * 32, 256), 256>>>(xc, b1, out_c, Nc);
    edge_aggr<<<cdivu((long)Ebc * 32, 256), 256>>>(wbuf, sbuf, b2c_src, b2c_dst, hs, out_c, Ebc);

    // ---------- GAT2: (updated) cable -> transformer ----------
    precompute_v<<<1, 128>>>(Wd2, ad2, v2);
    transpose_w_tf32<<<tg, tb>>>(Ws2, wt);
    gemm_mma<<<cdivu(Nc, 128), 256, MMA_SMEM>>>(out_c, wt, hs, Nc, es, as2);
    node_alpha<<<cdivu((long)Nt * 32, 256), 256>>>(xt, v2, ed, Nt);
    cudaMemsetAsync(sbuf, 0, (size_t)Nt * 4 * sizeof(float), 0);
    edge_w<<<cdivu(Ect, 256), 256>>>(es, ed, c2t_src, c2t_dst, wbuf, sbuf, Ect);
    init_half_bias<<<cdivu((long)Nt * 32, 256), 256>>>(xt, b2, out_t, Nt);
    edge_aggr<<<cdivu((long)Ect * 32, 256), 256>>>(wbuf, sbuf, c2t_src, c2t_dst, hs, out_t, Ect);

    // ---------- GCN: building adjacency (CSR gather) ----------
    int NBb = cdivu(Nb, SCAN_B);
    cudaMemsetAsync(cnt, 0, (size_t)Nb * sizeof(int), 0);
    count_dst<<<cdivu(Eadj, 256), 256>>>(adj_dst, cnt, Eadj);
    scan1<<<NBb, SCAN_B>>>(cnt, off, bsum, Nb);
    scan2<<<1, 1024>>>(bsum, NBb);
    scan3<<<NBb, SCAN_B>>>(cnt, off, bsum, dinv, Nb, Eadj);
    fill_csr<<<cdivu(Eadj, 256), 256>>>(adj_src, adj_dst, cnt, csrc, Eadj);
    transpose_w_tf32<<<tg, tb>>>(Wg, wt);
    gemm_mma<<<cdivu(Nb, 128), 256, MMA_SMEM>>>(xb, wt, hs, Nb, (float*)nullptr, bg);
    gcn_csr<<<cdivu((long)Nb * 32, 256), 256>>>(off, csrc, dinv, hs, xb, bg, out_b, Nb);
}

// round 7
// speedup vs baseline: 2.5615x; 1.1084x over previous
#include <cuda_runtime.h>
#include <cuda_bf16.h>
#include <cstdint>

// ---------------- scratch (device globals; no allocations allowed) ----------------
#define MAXNB 200000
#define MAXNC 20000
#define MAXE_GAT 200000
#define MAXE_ADJ 1600000
#define SCAN_B 512

__device__ __nv_bfloat16 g_hs[(size_t)MAXNB * 128];  // hs1, later hs2
__device__ __nv_bfloat16 g_xw[(size_t)MAXNB * 128];  // GCN xw
__device__ float g_es[(size_t)MAXNB * 4];
__device__ float g_ed[(size_t)MAXNC * 4];
__device__ float g_sb[(size_t)MAXNC * 4];
__device__ float g_wb[(size_t)MAXE_GAT * 4];
__device__ float g_dinv[MAXNB];
__device__ int   g_cnt[MAXNB];
__device__ int   g_off[MAXNB + 1];
__device__ int   g_bsum[1024];
__device__ int   g_csrc[MAXE_ADJ];
__device__ float g_v2a[128 * 4];
__device__ float g_v2b[128 * 4];
__device__ float g_wt1[128 * 128];
__device__ float g_wt2[128 * 128];
__device__ float g_wtg[128 * 128];

static __device__ __forceinline__ void red_add_v4(float* addr, float x, float y, float z, float w) {
    asm volatile("red.global.add.v4.f32 [%0], {%1,%2,%3,%4};"
                 :: "l"(addr), "f"(x), "f"(y), "f"(z), "f"(w) : "memory");
}

static __device__ __forceinline__ unsigned bf2pack(float c0, float c1) {
    unsigned r;
    asm("cvt.rn.bf16x2.f32 %0, %1, %2;" : "=r"(r) : "f"(c1), "f"(c0));
    return r;
}

static __device__ __forceinline__ uint32_t tf32r(float v) {
    uint32_t r;
    asm("cvt.rna.tf32.f32 %0, %1;" : "=r"(r) : "f"(v));
    return r;
}

// 3 weights transposed ([n][k]) + tf32-rounded, selected by blockIdx.z
__global__ void transpose_w3(const float* __restrict__ W0, const float* __restrict__ W1,
                             const float* __restrict__ W2, float* __restrict__ T0,
                             float* __restrict__ T1, float* __restrict__ T2) {
    const float* W = blockIdx.z == 0 ? W0 : (blockIdx.z == 1 ? W1 : W2);
    float* T = blockIdx.z == 0 ? T0 : (blockIdx.z == 1 ? T1 : T2);
    __shared__ float t[32][33];
    int bx = blockIdx.x * 32, by = blockIdx.y * 32;
#pragma unroll
    for (int j = 0; j < 32; j += 8)
        t[threadIdx.y + j][threadIdx.x] =
            __uint_as_float(tf32r(W[(size_t)(by + threadIdx.y + j) * 128 + bx + threadIdx.x]));
    __syncthreads();
#pragma unroll
    for (int j = 0; j < 32; j += 8)
        T[(size_t)(bx + threadIdx.y + j) * 128 + by + threadIdx.x] = t[threadIdx.x][threadIdx.y + j];
}

// V[d][h] = sum_c W[d, h*32+c] * a[h*32+c]; block 0 -> (Wd1,ad1,Va), block 1 -> (Wd2,ad2,Vb)
__global__ void precompute_v2(const float* __restrict__ Wd1, const float* __restrict__ ad1,
                              const float* __restrict__ Wd2, const float* __restrict__ ad2,
                              float* __restrict__ Va, float* __restrict__ Vb) {
    const float* W = blockIdx.x == 0 ? Wd1 : Wd2;
    const float* a = blockIdx.x == 0 ? ad1 : ad2;
    float* V = blockIdx.x == 0 ? Va : Vb;
    int d = threadIdx.x;
    float s[4] = {0.f, 0.f, 0.f, 0.f};
#pragma unroll
    for (int h = 0; h < 4; h++)
        for (int c = 0; c < 32; c++)
            s[h] += W[d * 128 + h * 32 + c] * a[h * 32 + c];
    ((float4*)V)[d] = make_float4(s[0], s[1], s[2], s[3]);
}

// ---------------- tf32 mma.sync GEMMs ----------------
#define AP 132
#define MMA_SMEM ((128 * AP * 2) * 4)

// shared mainloop: acc[16][4] += A_tile(warp) @ W_tile
static __device__ __forceinline__ void mma_loop(const uint32_t* Asu, const uint32_t* Wsu,
                                                int ar0, int ar1, int g, int t,
                                                float acc[16][4]) {
#pragma unroll 2
    for (int ks = 0; ks < 16; ks++) {
        int k0 = ks * 8;
        uint32_t a0 = Asu[ar0 + k0 + t];
        uint32_t a1 = Asu[ar1 + k0 + t];
        uint32_t a2 = Asu[ar0 + k0 + t + 4];
        uint32_t a3 = Asu[ar1 + k0 + t + 4];
#pragma unroll
        for (int nt = 0; nt < 16; nt++) {
            uint32_t b0 = Wsu[(nt * 8 + g) * AP + k0 + t];
            uint32_t b1 = Wsu[(nt * 8 + g) * AP + k0 + t + 4];
            asm("mma.sync.aligned.m16n8k8.row.col.f32.tf32.tf32.f32 "
                "{%0,%1,%2,%3}, {%4,%5,%6,%7}, {%8,%9}, {%0,%1,%2,%3};"
                : "+f"(acc[nt][0]), "+f"(acc[nt][1]), "+f"(acc[nt][2]), "+f"(acc[nt][3])
                : "r"(a0), "r"(a1), "r"(a2), "r"(a3), "r"(b0), "r"(b1));
        }
    }
}

static __device__ __forceinline__ void mma_epilogue(float acc[16][4], __nv_bfloat16* C, int M,
                                                    int grow0, int grow1, int t,
                                                    float* es_out, const float* a_s) {
    bool ok0 = grow0 < M, ok1 = grow1 < M;
    float s0[4] = {0.f, 0.f, 0.f, 0.f}, s1[4] = {0.f, 0.f, 0.f, 0.f};
#pragma unroll
    for (int nt = 0; nt < 16; nt++) {
        float c0 = acc[nt][0], c1 = acc[nt][1], c2 = acc[nt][2], c3 = acc[nt][3];
        int col = nt * 8 + 2 * t;
        if (ok0) *(unsigned*)(C + (size_t)grow0 * 128 + col) = bf2pack(c0, c1);
        if (ok1) *(unsigned*)(C + (size_t)grow1 * 128 + col) = bf2pack(c2, c3);
        if (es_out) {
            int h = nt >> 2;
            int cb = h * 32 + (nt & 3) * 8 + 2 * t;
            float av0 = __ldg(a_s + cb), av1 = __ldg(a_s + cb + 1);
            s0[h] += c0 * av0 + c1 * av1;
            s1[h] += c2 * av0 + c3 * av1;
        }
    }
    if (es_out) {
#pragma unroll
        for (int j = 0; j < 4; j++) {
            s0[j] += __shfl_down_sync(~0u, s0[j], 1);
            s0[j] += __shfl_down_sync(~0u, s0[j], 2);
            s1[j] += __shfl_down_sync(~0u, s1[j], 1);
            s1[j] += __shfl_down_sync(~0u, s1[j], 2);
        }
        if (t == 0) {
            if (ok0) ((float4*)es_out)[grow0] = make_float4(s0[0], s0[1], s0[2], s0[3]);
            if (ok1) ((float4*)es_out)[grow1] = make_float4(s1[0], s1[1], s1[2], s1[3]);
        }
    }
}

__global__ void __launch_bounds__(256, 1)
gemm_mma(const float* __restrict__ A, const float* __restrict__ Wt,
         __nv_bfloat16* __restrict__ C, int M,
         float* __restrict__ es_out, const float* __restrict__ a_s) {
    extern __shared__ float smem[];
    float* As = smem;
    float* Ws = smem + 128 * AP;
    int tid = threadIdx.x;
    int brow = blockIdx.x * 128;
    {
        int row = tid & 127;
        int k0 = (tid >> 7) * 64;
        int grow = brow + row;
        bool ok = grow < M;
        const float4* Ar = (const float4*)(A + (size_t)grow * 128 + k0);
        const float4* Wr = (const float4*)(Wt + (size_t)row * 128 + k0);
#pragma unroll
        for (int i = 0; i < 16; i++) {
            float4 v = make_float4(0.f, 0.f, 0.f, 0.f);
            if (ok) v = Ar[i];
            uint4 tv;
            tv.x = tf32r(v.x); tv.y = tf32r(v.y); tv.z = tf32r(v.z); tv.w = tf32r(v.w);
            *(uint4*)(As + row * AP + k0 + i * 4) = tv;
            *(float4*)(Ws + row * AP + k0 + i * 4) = Wr[i];
        }
    }
    __syncthreads();

    int wid = tid >> 5, lane = tid & 31;
    int g = lane >> 2, t = lane & 3;
    int wbase = wid * 16;
    float acc[16][4];
#pragma unroll
    for (int nt = 0; nt < 16; nt++)
#pragma unroll
        for (int j = 0; j < 4; j++) acc[nt][j] = 0.f;
    mma_loop((const uint32_t*)As, (const uint32_t*)Ws,
             (wbase + g) * AP, (wbase + g + 8) * AP, g, t, acc);
    mma_epilogue(acc, C, M, brow + wbase + g, brow + wbase + g + 8, t, es_out, a_s);
}

// dual-weight GEMM: stage A once, two weight phases (C0/es from Wt0, C1 from Wt1)
__global__ void __launch_bounds__(256, 1)
gemm_dual(const float* __restrict__ A, const float* __restrict__ Wt0,
          const float* __restrict__ Wt1, __nv_bfloat16* __restrict__ C0,
          __nv_bfloat16* __restrict__ C1, int M,
          float* __restrict__ es_out, const float* __restrict__ a_s) {
    extern __shared__ float smem[];
    float* As = smem;
    float* Ws = smem + 128 * AP;
    int tid = threadIdx.x;
    int brow = blockIdx.x * 128;
    int row = tid & 127;
    int k0 = (tid >> 7) * 64;
    {
        int grow = brow + row;
        bool ok = grow < M;
        const float4* Ar = (const float4*)(A + (size_t)grow * 128 + k0);
#pragma unroll
        for (int i = 0; i < 16; i++) {
            float4 v = make_float4(0.f, 0.f, 0.f, 0.f);
            if (ok) v = Ar[i];
            uint4 tv;
            tv.x = tf32r(v.x); tv.y = tf32r(v.y); tv.z = tf32r(v.z); tv.w = tf32r(v.w);
            *(uint4*)(As + row * AP + k0 + i * 4) = tv;
        }
    }

    int wid = tid >> 5, lane = tid & 31;
    int g = lane >> 2, t = lane & 3;
    int wbase = wid * 16;
    int ar0 = (wbase + g) * AP, ar1 = (wbase + g + 8) * AP;

#pragma unroll
    for (int p = 0; p < 2; p++) {
        const float* Wt = p == 0 ? Wt0 : Wt1;
        {
            const float4* Wr = (const float4*)(Wt + (size_t)row * 128 + k0);
#pragma unroll
            for (int i = 0; i < 16; i++)
                *(float4*)(Ws + row * AP + k0 + i * 4) = Wr[i];
        }
        __syncthreads();
        float acc[16][4];
#pragma unroll
        for (int nt = 0; nt < 16; nt++)
#pragma unroll
            for (int j = 0; j < 4; j++) acc[nt][j] = 0.f;
        mma_loop((const uint32_t*)As, (const uint32_t*)Ws, ar0, ar1, g, t, acc);
        __syncthreads();  // safe to overwrite Ws next phase
        mma_epilogue(acc, p == 0 ? C0 : C1, M, brow + wbase + g, brow + wbase + g + 8, t,
                     p == 0 ? es_out : (float*)nullptr, a_s);
    }
}

// out[n,h] = x[n,:] @ V[:,h]   (warp per node)
__global__ void node_alpha(const float* __restrict__ X, const float* __restrict__ V,
                           float* __restrict__ out, int N) {
    int gt = blockIdx.x * blockDim.x + threadIdx.x;
    int n = gt >> 5, lane = gt & 31;
    if (n >= N) return;
    float4 x = ((const float4*)(X + (size_t)n * 128))[lane];
    const float4* Vv = (const float4*)V;
    float xv[4] = {x.x, x.y, x.z, x.w};
    float s0 = 0.f, s1 = 0.f, s2 = 0.f, s3 = 0.f;
#pragma unroll
    for (int j = 0; j < 4; j++) {
        float4 v = Vv[lane * 4 + j];
        s0 += xv[j] * v.x; s1 += xv[j] * v.y;
        s2 += xv[j] * v.z; s3 += xv[j] * v.w;
    }
#pragma unroll
    for (int off = 16; off; off >>= 1) {
        s0 += __shfl_down_sync(~0u, s0, off);
        s1 += __shfl_down_sync(~0u, s1, off);
        s2 += __shfl_down_sync(~0u, s2, off);
        s3 += __shfl_down_sync(~0u, s3, off);
    }
    if (lane == 0) ((float4*)out)[n] = make_float4(s0, s1, s2, s3);
}

static __device__ __forceinline__ float4 edge_w4(const float* es, const float* ed, int s, int d) {
    float4 a = ((const float4*)es)[s];
    float4 b = ((const float4*)ed)[d];
    float t0 = a.x + b.x, t1 = a.y + b.y, t2 = a.z + b.z, t3 = a.w + b.w;
    t0 = t0 > 0.f ? t0 : 0.2f * t0;
    t1 = t1 > 0.f ? t1 : 0.2f * t1;
    t2 = t2 > 0.f ? t2 : 0.2f * t2;
    t3 = t3 > 0.f ? t3 : 0.2f * t3;
    return make_float4(__expf(t0), __expf(t1), __expf(t2), __expf(t3));
}

// COO edge_w for GAT2 (small)
__global__ void edge_w(const float* __restrict__ es, const float* __restrict__ ed,
                       const int* __restrict__ src, const int* __restrict__ dst,
                       float* __restrict__ w, float* __restrict__ ssum, int E) {
    int e = blockIdx.x * blockDim.x + threadIdx.x;
    if (e >= E) return;
    int s = src[e], d = dst[e];
    float4 wv = edge_w4(es, ed, s, d);
    ((float4*)w)[e] = wv;
    red_add_v4(ssum + (size_t)d * 4, wv.x, wv.y, wv.z, wv.w);
}

// CSR edge_w + fill for GAT1
__global__ void edge_w_fill(const float* __restrict__ es, const float* __restrict__ ed,
                            const int* __restrict__ src, const int* __restrict__ dst,
                            int* __restrict__ cursor, int* __restrict__ csrc,
                            float* __restrict__ w, int E) {
    int e = blockIdx.x * blockDim.x + threadIdx.x;
    if (e >= E) return;
    int s = src[e], d = dst[e];
    float4 wv = edge_w4(es, ed, s, d);
    int p = atomicAdd(cursor + d, 1);
    csrc[p] = s;
    ((float4*)w)[p] = wv;
}

// warp per dst node: softmax-sum + gather + finalize  (out = xdst + 0.5*bias + sum 0.5*alpha*hs)
__global__ void gat_csr(const int* __restrict__ off, const int* __restrict__ csrc,
                        const float* __restrict__ wbuf, const __nv_bfloat16* __restrict__ hs,
                        const float* __restrict__ xdst, const float* __restrict__ bias,
                        float* __restrict__ out, int N) {
    int gt = blockIdx.x * blockDim.x + threadIdx.x;
    int n = gt >> 5, lane = gt & 31;
    if (n >= N) return;
    int o0 = off[n], o1 = off[n + 1];
    float sw0 = 0.f, sw1 = 0.f, sw2 = 0.f, sw3 = 0.f;
    for (int e = o0 + lane; e < o1; e += 32) {
        float4 w = ((const float4*)wbuf)[e];
        sw0 += w.x; sw1 += w.y; sw2 += w.z; sw3 += w.w;
    }
#pragma unroll
    for (int o = 16; o; o >>= 1) {
        sw0 += __shfl_xor_sync(~0u, sw0, o);
        sw1 += __shfl_xor_sync(~0u, sw1, o);
        sw2 += __shfl_xor_sync(~0u, sw2, o);
        sw3 += __shfl_xor_sync(~0u, sw3, o);
    }
    int h = lane >> 3;
    float stot = (h < 2) ? (h == 0 ? sw0 : sw1) : (h == 2 ? sw2 : sw3);
    float kinv = 0.5f / (stot + 1e-16f);
    float a0 = 0.f, a1 = 0.f, a2 = 0.f, a3 = 0.f;
    for (int base = o0; base < o1; base += 32) {
        int eidx = base + lane;
        bool v = eidx < o1;
        int s_l = v ? csrc[eidx] : 0;
        float4 w_l = v ? ((const float4*)wbuf)[eidx] : make_float4(0.f, 0.f, 0.f, 0.f);
        int cntc = min(32, o1 - base);
        for (int j = 0; j < cntc; j++) {
            int s = __shfl_sync(~0u, s_l, j);
            float w0 = __shfl_sync(~0u, w_l.x, j);
            float w1 = __shfl_sync(~0u, w_l.y, j);
            float w2 = __shfl_sync(~0u, w_l.z, j);
            float w3 = __shfl_sync(~0u, w_l.w, j);
            float wh = (h < 2) ? (h == 0 ? w0 : w1) : (h == 2 ? w2 : w3);
            float k = wh * kinv;
            uint2 raw = *(const uint2*)(hs + (size_t)s * 128 + lane * 4);
            float2 f0 = __bfloat1622float2(*(const __nv_bfloat162*)&raw.x);
            float2 f1 = __bfloat1622float2(*(const __nv_bfloat162*)&raw.y);
            a0 += k * f0.x; a1 += k * f0.y; a2 += k * f1.x; a3 += k * f1.y;
        }
    }
    float4 xv = *(const float4*)(xdst + (size_t)n * 128 + lane * 4);
    float4 bv = *(const float4*)(bias + lane * 4);
    float4 o;
    o.x = xv.x + 0.5f * bv.x + a0;
    o.y = xv.y + 0.5f * bv.y + a1;
    o.z = xv.z + 0.5f * bv.z + a2;
    o.w = xv.w + 0.5f * bv.w + a3;
    *(float4*)(out + (size_t)n * 128 + lane * 4) = o;
}

// warp per edge: out[dst] += 0.5 * alpha * hs_bf16[src]  (COO, GAT2)
__global__ void edge_aggr(const float* __restrict__ w, const float* __restrict__ ssum,
                          const int* __restrict__ src, const int* __restrict__ dst,
                          const __nv_bfloat16* __restrict__ hs, float* __restrict__ out, int E) {
    int gt = blockIdx.x * blockDim.x + threadIdx.x;
    int e = gt >> 5, lane = gt & 31;
    if (e >= E) return;
    int s = src[e], d = dst[e];
    int h = lane >> 3;
    float alpha = w[(size_t)e * 4 + h] / (ssum[(size_t)d * 4 + h] + 1e-16f);
    float k = 0.5f * alpha;
    uint2 raw = *(const uint2*)(hs + (size_t)s * 128 + lane * 4);
    float2 f0 = __bfloat1622float2(*(const __nv_bfloat162*)&raw.x);
    float2 f1 = __bfloat1622float2(*(const __nv_bfloat162*)&raw.y);
    red_add_v4(out + (size_t)d * 128 + lane * 4, k * f0.x, k * f0.y, k * f1.x, k * f1.y);
}

// out[n,c] = x[n,c] + 0.5*b[c]
__global__ void init_half_bias(const float* __restrict__ x, const float* __restrict__ b,
                               float* __restrict__ out, int N) {
    int i = blockIdx.x * blockDim.x + threadIdx.x;
    if (i >= N * 32) return;
    float4 xv = ((const float4*)x)[i];
    float4 bv = ((const float4*)b)[i & 31];
    ((float4*)out)[i] = make_float4(xv.x + 0.5f * bv.x, xv.y + 0.5f * bv.y,
                                    xv.z + 0.5f * bv.z, xv.w + 0.5f * bv.w);
}

// ---------------- CSR build ----------------
__global__ void count_dst(const int* __restrict__ dst, int* __restrict__ cnt, int E) {
    int e = blockIdx.x * blockDim.x + threadIdx.x;
    if (e < E) atomicAdd(cnt + dst[e], 1);
}

__global__ void scan1(const int* __restrict__ cnt, int* __restrict__ incl,
                      int* __restrict__ bsum, int N) {
    int i = blockIdx.x * SCAN_B + threadIdx.x;
    int lane = threadIdx.x & 31, wid = threadIdx.x >> 5;
    int v = (i < N) ? cnt[i] : 0;
    int x = v;
#pragma unroll
    for (int o = 1; o < 32; o <<= 1) {
        int t = __shfl_up_sync(~0u, x, o);
        if (lane >= o) x += t;
    }
    __shared__ int wtot[16];
    if (lane == 31) wtot[wid] = x;
    __syncthreads();
    if (wid == 0) {
        int t = (lane < 16) ? wtot[lane] : 0;
#pragma unroll
        for (int o = 1; o < 16; o <<= 1) {
            int u = __shfl_up_sync(~0u, t, o);
            if (lane >= o) t += u;
        }
        if (lane < 16) wtot[lane] = t;
    }
    __syncthreads();
    int base = (wid > 0) ? wtot[wid - 1] : 0;
    int inclv = x + base;
    if (i < N) incl[i] = inclv;
    if (threadIdx.x == SCAN_B - 1) bsum[blockIdx.x] = inclv;
}

__global__ void scan2(int* __restrict__ bsum, int NB) {
    int i = threadIdx.x;
    int lane = i & 31, wid = i >> 5;
    int v = (i < NB) ? bsum[i] : 0;
    int x = v;
#pragma unroll
    for (int o = 1; o < 32; o <<= 1) {
        int t = __shfl_up_sync(~0u, x, o);
        if (lane >= o) x += t;
    }
    __shared__ int wtot[32];
    if (lane == 31) wtot[wid] = x;
    __syncthreads();
    if (wid == 0) {
        int t = wtot[lane];
#pragma unroll
        for (int o = 1; o < 32; o <<= 1) {
            int u = __shfl_up_sync(~0u, t, o);
            if (lane >= o) t += u;
        }
        wtot[lane] = t;
    }
    __syncthreads();
    int base = (wid > 0) ? wtot[wid - 1] : 0;
    if (i < NB) bsum[i] = x + base - v;
}

__global__ void scan3(int* __restrict__ cnt_cursor, int* __restrict__ off,
                      const int* __restrict__ bsum, float* __restrict__ dinv,
                      int N, int E) {
    int i = blockIdx.x * SCAN_B + threadIdx.x;
    if (i >= N) return;
    int c = cnt_cursor[i];
    int excl = off[i] - c + bsum[blockIdx.x];
    off[i] = excl;
    cnt_cursor[i] = excl;
    if (dinv) dinv[i] = rsqrtf((float)c + 1.0f);
    if (i == N - 1) off[N] = E;
}

__global__ void fill_csr(const int* __restrict__ src, const int* __restrict__ dst,
                         int* __restrict__ cursor, int* __restrict__ csrc, int E) {
    int e = blockIdx.x * blockDim.x + threadIdx.x;
    if (e >= E) return;
    int d = dst[e];
    int p = atomicAdd(cursor + d, 1);
    csrc[p] = src[e];
}

// warp per dst node: GCN gather + finalize
__global__ void gcn_csr(const int* __restrict__ off, const int* __restrict__ csrc,
                        const float* __restrict__ dinv, const __nv_bfloat16* __restrict__ xw,
                        const float* __restrict__ xb, const float* __restrict__ bg,
                        float* __restrict__ out, int N) {
    int gt = blockIdx.x * blockDim.x + threadIdx.x;
    int n = gt >> 5, lane = gt & 31;
    if (n >= N) return;
    int o0 = off[n], o1 = off[n + 1];
    float a0 = 0.f, a1 = 0.f, a2 = 0.f, a3 = 0.f;
    for (int base = o0; base < o1; base += 32) {
        int eidx = base + lane;
        bool v = eidx < o1;
        int s_l = v ? csrc[eidx] : 0;
        float ds_l = v ? dinv[s_l] : 0.f;
        int cntc = min(32, o1 - base);
        for (int j = 0; j < cntc; j++) {
            int s = __shfl_sync(~0u, s_l, j);
            float ds = __shfl_sync(~0u, ds_l, j);
            uint2 raw = *(const uint2*)(xw + (size_t)s * 128 + lane * 4);
            float2 f0 = __bfloat1622float2(*(const __nv_bfloat162*)&raw.x);
            float2 f1 = __bfloat1622float2(*(const __nv_bfloat162*)&raw.y);
            a0 += ds * f0.x; a1 += ds * f0.y; a2 += ds * f1.x; a3 += ds * f1.y;
        }
    }
    float dn = dinv[n];
    float dd = dn * dn;
    float4 xv = *(const float4*)(xb + (size_t)n * 128 + lane * 4);
    uint2 rw = *(const uint2*)(xw + (size_t)n * 128 + lane * 4);
    float2 s0 = __bfloat1622float2(*(const __nv_bfloat162*)&rw.x);
    float2 s1 = __bfloat1622float2(*(const __nv_bfloat162*)&rw.y);
    float4 bv = *(const float4*)(bg + lane * 4);
    float4 o;
    o.x = xv.x + 0.2f * (dn * a0 + dd * s0.x + bv.x);
    o.y = xv.y + 0.2f * (dn * a1 + dd * s0.y + bv.y);
    o.z = xv.z + 0.2f * (dn * a2 + dd * s1.x + bv.z);
    o.w = xv.w + 0.2f * (dn * a3 + dd * s1.y + bv.w);
    *(float4*)(out + (size_t)n * 128 + lane * 4) = o;
}

// ---------------- launcher ----------------
static inline unsigned cdivu(long a, long b) { return (unsigned)((a + b - 1) / b); }

extern "C" void kernel_launch(void* const* d_in, const int* in_sizes, int n_in,
                              void* d_out, int out_size) {
    const float* xb  = (const float*)d_in[0];
    const float* xc  = (const float*)d_in[1];
    const float* xt  = (const float*)d_in[2];
    const float* Ws1 = (const float*)d_in[3];
    const float* Wd1 = (const float*)d_in[4];
    const float* as1 = (const float*)d_in[5];
    const float* ad1 = (const float*)d_in[6];
    const float* b1  = (const float*)d_in[7];
    const float* Ws2 = (const float*)d_in[8];
    const float* Wd2 = (const float*)d_in[9];
    const float* as2 = (const float*)d_in[10];
    const float* ad2 = (const float*)d_in[11];
    const float* b2  = (const float*)d_in[12];
    const float* Wg  = (const float*)d_in[13];
    const float* bg  = (const float*)d_in[14];
    const int* b2c_src = (const int*)d_in[15];
    const int* b2c_dst = (const int*)d_in[16];
    const int* c2t_src = (const int*)d_in[17];
    const int* c2t_dst = (const int*)d_in[18];
    const int* adj_src = (const int*)d_in[19];
    const int* adj_dst = (const int*)d_in[20];

    int Nb = in_sizes[0] / 128, Nc = in_sizes[1] / 128, Nt = in_sizes[2] / 128;
    int Ebc = in_sizes[15], Ect = in_sizes[17], Eadj = in_sizes[19];

    float* out   = (float*)d_out;
    float* out_b = out;
    float* out_c = out + (size_t)Nb * 128;
    float* out_t = out_c + (size_t)Nc * 128;

    void* p;
    cudaGetSymbolAddress(&p, g_hs);   __nv_bfloat16* hs = (__nv_bfloat16*)p;
    cudaGetSymbolAddress(&p, g_xw);   __nv_bfloat16* xw = (__nv_bfloat16*)p;
    cudaGetSymbolAddress(&p, g_es);   float* es   = (float*)p;
    cudaGetSymbolAddress(&p, g_ed);   float* ed   = (float*)p;
    cudaGetSymbolAddress(&p, g_sb);   float* sbuf = (float*)p;
    cudaGetSymbolAddress(&p, g_wb);   float* wbuf = (float*)p;
    cudaGetSymbolAddress(&p, g_dinv); float* dinv = (float*)p;
    cudaGetSymbolAddress(&p, g_cnt);  int*   cnt  = (int*)p;
    cudaGetSymbolAddress(&p, g_off);  int*   off  = (int*)p;
    cudaGetSymbolAddress(&p, g_bsum); int*   bsum = (int*)p;
    cudaGetSymbolAddress(&p, g_csrc); int*   csrc = (int*)p;
    cudaGetSymbolAddress(&p, g_v2a);  float* v2a  = (float*)p;
    cudaGetSymbolAddress(&p, g_v2b);  float* v2b  = (float*)p;
    cudaGetSymbolAddress(&p, g_wt1);  float* wt1  = (float*)p;
    cudaGetSymbolAddress(&p, g_wt2);  float* wt2  = (float*)p;
    cudaGetSymbolAddress(&p, g_wtg);  float* wtg  = (float*)p;

    cudaFuncSetAttribute(gemm_mma, cudaFuncAttributeMaxDynamicSharedMemorySize, MMA_SMEM);
    cudaFuncSetAttribute(gemm_dual, cudaFuncAttributeMaxDynamicSharedMemorySize, MMA_SMEM);

    // prep: weights
    precompute_v2<<<2, 128>>>(Wd1, ad1, Wd2, ad2, v2a, v2b);
    transpose_w3<<<dim3(4, 4, 3), dim3(32, 8)>>>(Ws1, Ws2, Wg, wt1, wt2, wtg);

    // fused xb GEMMs: hs1 (+es) and xw
    gemm_dual<<<cdivu(Nb, 128), 256, MMA_SMEM>>>(xb, wt1, wtg, hs, xw, Nb, es, as1);

    // ---------- GAT1: building -> cable (CSR) ----------
    node_alpha<<<cdivu((long)Nc * 32, 256), 256>>>(xc, v2a, ed, Nc);
    int NCb = cdivu(Nc, SCAN_B);
    cudaMemsetAsync(cnt, 0, (size_t)Nc * sizeof(int), 0);
    count_dst<<<cdivu(Ebc, 256), 256>>>(b2c_dst, cnt, Ebc);
    scan1<<<NCb, SCAN_B>>>(cnt, off, bsum, Nc);
    scan2<<<1, 1024>>>(bsum, NCb);
    scan3<<<NCb, SCAN_B>>>(cnt, off, bsum, (float*)nullptr, Nc, Ebc);
    edge_w_fill<<<cdivu(Ebc, 256), 256>>>(es, ed, b2c_src, b2c_dst, cnt, csrc, wbuf, Ebc);
    gat_csr<<<cdivu((long)Nc * 32, 256), 256>>>(off, csrc, wbuf, hs, xc, b1, out_c, Nc);

    // ---------- GAT2: cable -> transformer (COO, small) ----------
    gemm_mma<<<cdivu(Nc, 128), 256, MMA_SMEM>>>(out_c, wt2, hs, Nc, es, as2);
    node_alpha<<<cdivu((long)Nt * 32, 256), 256>>>(xt, v2b, ed, Nt);
    cudaMemsetAsync(sbuf, 0, (size_t)Nt * 4 * sizeof(float), 0);
    edge_w<<<cdivu(Ect, 256), 256>>>(es, ed, c2t_src, c2t_dst, wbuf, sbuf, Ect);
    init_half_bias<<<cdivu((long)Nt * 32, 256), 256>>>(xt, b2, out_t, Nt);
    edge_aggr<<<cdivu((long)Ect * 32, 256), 256>>>(wbuf, sbuf, c2t_src, c2t_dst, hs, out_t, Ect);

    // ---------- GCN: building adjacency (CSR gather) ----------
    int NBb = cdivu(Nb, SCAN_B);
    cudaMemsetAsync(cnt, 0, (size_t)Nb * sizeof(int), 0);
    count_dst<<<cdivu(Eadj, 256), 256>>>(adj_dst, cnt, Eadj);
    scan1<<<NBb, SCAN_B>>>(cnt, off, bsum, Nb);
    scan2<<<1, 1024>>>(bsum, NBb);
    scan3<<<NBb, SCAN_B>>>(cnt, off, bsum, dinv, Nb, Eadj);
    fill_csr<<<cdivu(Eadj, 256), 256>>>(adj_src, adj_dst, cnt, csrc, Eadj);
    gcn_csr<<<cdivu((long)Nb * 32, 256), 256>>>(off, csrc, dinv, xw, xb, bg, out_b, Nb);
}